// round 5
// baseline (speedup 1.0000x reference)
#include <cuda_runtime.h>
#include <cstdint>

#define BATCH 32768
#define PITCH 36
#define A_WORDS (128 * PITCH)

// ---------------- device scratch (static, allocation-free) ----------------
__device__ __align__(128) float g_W1[576 * 256];           // [Wq^T(64) | Wg(256) | Wo1(256)] tf32-rounded
__device__ __align__(128) float g_W2[256 * 256];           // Wo2 (tf32-rounded)
__device__ __align__(128) float g_Wk2[256 * 64];           // Wk^T: [e][a] (tf32-rounded)
__device__ __align__(128) float g_q[(size_t)BATCH * 64];   // q = C Wq^T
__device__ __align__(128) float g_E[(size_t)BATCH * 768];  // P | gate | E1
__device__ __align__(128) float g_ctx[(size_t)BATCH * 256];

// ---------------- helpers --------------------------------------------------
__device__ __forceinline__ float rnd_tf32(float x) {
    uint32_t y;
    asm("cvt.rna.tf32.f32 %0, %1;" : "=r"(y) : "f"(x));
    return __uint_as_float(y);
}
__device__ __forceinline__ void cp_async16(void* smem_dst, const void* gmem_src) {
    uint32_t s = (uint32_t)__cvta_generic_to_shared(smem_dst);
    asm volatile("cp.async.cg.shared.global [%0], [%1], 16;\n" :: "r"(s), "l"(gmem_src));
}
__device__ __forceinline__ void ldsm_x4(uint32_t& r0, uint32_t& r1, uint32_t& r2, uint32_t& r3,
                                        uint32_t saddr) {
    asm volatile("ldmatrix.sync.aligned.m8n8.x4.shared.b16 {%0,%1,%2,%3}, [%4];"
                 : "=r"(r0), "=r"(r1), "=r"(r2), "=r"(r3) : "r"(saddr));
}
__device__ __forceinline__ float warp_sum(float v) {
    v += __shfl_xor_sync(0xffffffffu, v, 16);
    v += __shfl_xor_sync(0xffffffffu, v, 8);
    v += __shfl_xor_sync(0xffffffffu, v, 4);
    v += __shfl_xor_sync(0xffffffffu, v, 2);
    v += __shfl_xor_sync(0xffffffffu, v, 1);
    return v;
}

// ---------------- K0: build fused weight matrices (pure copies) -----------
__global__ void prep_kernel(const float* __restrict__ Wq, const float* __restrict__ Wk,
                            const float* __restrict__ Wg, const float* __restrict__ Wo) {
    int j = blockIdx.x;
    int e = threadIdx.x;
    if (j < 64)        g_W1[j * 256 + e] = rnd_tf32(Wq[j * 256 + e]);
    else if (j < 320)  g_W1[j * 256 + e] = rnd_tf32(Wg[(j - 64) * 256 + e]);
    else if (j < 576)  g_W1[j * 256 + e] = rnd_tf32(Wo[(j - 320) * 512 + e]);
    else if (j < 832)  g_W2[(j - 576) * 256 + e] = rnd_tf32(Wo[(j - 576) * 512 + 256 + e]);
    else if (e < 64)   g_Wk2[(j - 832) * 64 + e] = rnd_tf32(Wk[e * 256 + (j - 832)]);
}

// ---------------- GEMM: tf32 mma.sync, 3-stage cp.async, 1 sync/iter ------
// Warp tile 32x64; warp grid 4M x (NTH/128)N.
// MODE 0: A = gathered centers (K=256), B = g_W1, N-slab 192 -> q/gate/E1
// MODE 1: A = g_ctx (K=256), B = g_W2, epilogue + E1 + center + fused LN -> out
// MODE 2: A = g_q (K=64),  B = g_Wk2, raw -> g_E P slab
template <int MODE, int BROWS, int NK, int NTH>
__global__ __launch_bounds__(NTH, 1)
void gemm_kernel(const float* __restrict__ all_embs,
                 const int* __restrict__ center_idx,
                 const float* __restrict__ bg,
                 const float* __restrict__ bo,
                 const float* __restrict__ gamma,
                 const float* __restrict__ beta,
                 float* __restrict__ out) {
    constexpr int STAGE_WORDS = (128 + BROWS) * PITCH;
    extern __shared__ float sm[];
    __shared__ int   ridx[128];
    __shared__ float redS[128][4];
    __shared__ float redQ[128][4];

    const int t    = threadIdx.x;
    const int lane = t & 31;
    const int warp = t >> 5;
    const int m0 = blockIdx.x * 128;
    const int n0 = blockIdx.y * ((MODE == 0) ? 192 : 256);
    const float* Bmat = (MODE == 0) ? g_W1 : ((MODE == 1) ? g_W2 : g_Wk2);
    constexpr int BSTRIDE = (MODE == 2) ? 64 : 256;

    if (MODE != 2 && t < 128) ridx[t] = center_idx[m0 + t];
    __syncthreads();

    const uint32_t sm_u32 = (uint32_t)__cvta_generic_to_shared(sm);

    const int g   = lane >> 2;
    const int tg  = lane & 3;
    const int mb  = (warp & 3) * 32;
    const int nbo = (warp >> 2) * 64;

    uint32_t a_off[2], b_off[4];
#pragma unroll
    for (int mt = 0; mt < 2; mt++)
        a_off[mt] = ((mb + mt * 16 + (lane & 15)) * PITCH + ((lane >> 4) & 1) * 4) * 4;
#pragma unroll
    for (int p = 0; p < 4; p++)
        b_off[p] = (A_WORDS + (nbo + p * 16 + ((lane >> 4) & 1) * 8 + (lane & 7)) * PITCH
                    + ((lane >> 3) & 1) * 4) * 4;

    auto fill = [&](int kt, int s) {
        float* base = sm + s * STAGE_WORDS;
        const int kk = kt * 32;
        for (int idx = t; idx < 128 * 8; idx += NTH) {
            int row = idx >> 3, ch = (idx & 7) * 4;
            const float* src;
            if (MODE == 0)      src = all_embs + (size_t)ridx[row] * 256 + kk + ch;
            else if (MODE == 1) src = g_ctx + (size_t)(m0 + row) * 256 + kk + ch;
            else                src = g_q + (size_t)(m0 + row) * 64 + kk + ch;
            cp_async16(base + row * PITCH + ch, src);
        }
        for (int idx = t; idx < BROWS * 8; idx += NTH) {
            int row = idx >> 3, ch = (idx & 7) * 4;
            cp_async16(base + A_WORDS + row * PITCH + ch,
                       Bmat + (size_t)(n0 + row) * BSTRIDE + kk + ch);
        }
    };

    float acc[2][8][4] = {};

    fill(0, 0);
    asm volatile("cp.async.commit_group;\n" ::: "memory");
    fill(1, 1);
    asm volatile("cp.async.commit_group;\n" ::: "memory");

#pragma unroll 1
    for (int it = 0; it < NK; ++it) {
        const int s = it % 3;
        if (it + 1 < NK) asm volatile("cp.async.wait_group 1;\n" ::: "memory");
        else             asm volatile("cp.async.wait_group 0;\n" ::: "memory");
        __syncthreads();
        if (it + 2 < NK) {
            fill(it + 2, (it + 2) % 3);
            asm volatile("cp.async.commit_group;\n" ::: "memory");
        }

        const uint32_t stage = sm_u32 + s * (STAGE_WORDS * 4);
#pragma unroll
        for (int ks = 0; ks < 4; ks++) {
            const uint32_t kbyte = ks * 32;
            uint32_t a[2][4];
#pragma unroll
            for (int mt = 0; mt < 2; mt++)
                ldsm_x4(a[mt][0], a[mt][1], a[mt][2], a[mt][3], stage + a_off[mt] + kbyte);
            uint32_t bf[8][2];
#pragma unroll
            for (int p = 0; p < 4; p++)
                ldsm_x4(bf[2 * p][0], bf[2 * p][1], bf[2 * p + 1][0], bf[2 * p + 1][1],
                        stage + b_off[p] + kbyte);
#pragma unroll
            for (int mt = 0; mt < 2; mt++)
#pragma unroll
                for (int nt = 0; nt < 8; nt++)
                    asm volatile(
                        "mma.sync.aligned.m16n8k8.row.col.f32.tf32.tf32.f32 "
                        "{%0,%1,%2,%3}, {%4,%5,%6,%7}, {%8,%9}, {%0,%1,%2,%3};\n"
                        : "+f"(acc[mt][nt][0]), "+f"(acc[mt][nt][1]),
                          "+f"(acc[mt][nt][2]), "+f"(acc[mt][nt][3])
                        : "r"(a[mt][0]), "r"(a[mt][1]), "r"(a[mt][2]), "r"(a[mt][3]),
                          "r"(bf[nt][0]), "r"(bf[nt][1]));
        }
    }

    if (MODE == 0) {
#pragma unroll
        for (int mt = 0; mt < 2; mt++)
#pragma unroll
            for (int nt = 0; nt < 8; nt++) {
                int j = n0 + nbo + nt * 8 + tg * 2;   // global col in [0,576)
#pragma unroll
                for (int h = 0; h < 2; h++) {
                    int row = m0 + mb + mt * 16 + g + h * 8;
                    float v0 = acc[mt][nt][h * 2 + 0];
                    float v1 = acc[mt][nt][h * 2 + 1];
                    if (j < 64) {
                        *(float2*)(g_q + (size_t)row * 64 + j) = make_float2(v0, v1);
                    } else if (j < 320) {
                        v0 = 1.f / (1.f + __expf(-(v0 + bg[j - 64])));
                        v1 = 1.f / (1.f + __expf(-(v1 + bg[j - 63])));
                        *(float2*)(g_E + (size_t)row * 768 + 256 + (j - 64)) = make_float2(v0, v1);
                    } else {
                        v0 += bo[j - 320];
                        v1 += bo[j - 319];
                        *(float2*)(g_E + (size_t)row * 768 + 512 + (j - 320)) = make_float2(v0, v1);
                    }
                }
            }
    } else if (MODE == 2) {
#pragma unroll
        for (int mt = 0; mt < 2; mt++)
#pragma unroll
            for (int nt = 0; nt < 8; nt++) {
                int j = nbo + nt * 8 + tg * 2;
#pragma unroll
                for (int h = 0; h < 2; h++) {
                    int row = m0 + mb + mt * 16 + g + h * 8;
                    *(float2*)(g_E + (size_t)row * 768 + j) =
                        make_float2(acc[mt][nt][h * 2 + 0], acc[mt][nt][h * 2 + 1]);
                }
            }
    } else {
        // MODE 1: add E1 + center, fused LayerNorm
        float rs[4] = {0.f, 0.f, 0.f, 0.f};
        float rq[4] = {0.f, 0.f, 0.f, 0.f};
#pragma unroll
        for (int mt = 0; mt < 2; mt++)
#pragma unroll
            for (int h = 0; h < 2; h++) {
                int lr = mb + mt * 16 + g + h * 8;
                int row = m0 + lr;
                const float* cen = all_embs + (size_t)ridx[lr] * 256;
                const float* e1r = g_E + (size_t)row * 768 + 512;
                float s = 0.f, q = 0.f;
#pragma unroll
                for (int nt = 0; nt < 8; nt++) {
                    int j = nbo + nt * 8 + tg * 2;
                    float2 e1 = *(const float2*)(e1r + j);
                    float2 c2 = *(const float2*)(cen + j);
                    float v0 = acc[mt][nt][h * 2 + 0] + e1.x + c2.x;
                    float v1 = acc[mt][nt][h * 2 + 1] + e1.y + c2.y;
                    acc[mt][nt][h * 2 + 0] = v0;
                    acc[mt][nt][h * 2 + 1] = v1;
                    s += v0 + v1;
                    q += v0 * v0 + v1 * v1;
                }
                rs[mt * 2 + h] = s;
                rq[mt * 2 + h] = q;
            }
#pragma unroll
        for (int i = 0; i < 4; i++) {
            rs[i] += __shfl_xor_sync(0xffffffffu, rs[i], 1);
            rs[i] += __shfl_xor_sync(0xffffffffu, rs[i], 2);
            rq[i] += __shfl_xor_sync(0xffffffffu, rq[i], 1);
            rq[i] += __shfl_xor_sync(0xffffffffu, rq[i], 2);
        }
        const int nw = warp >> 2;
        if (tg == 0) {
#pragma unroll
            for (int mt = 0; mt < 2; mt++)
#pragma unroll
                for (int h = 0; h < 2; h++) {
                    int lr = mb + mt * 16 + g + h * 8;
                    redS[lr][nw] = rs[mt * 2 + h];
                    redQ[lr][nw] = rq[mt * 2 + h];
                }
        }
        __syncthreads();
        float mu[4], rstd[4];
#pragma unroll
        for (int mt = 0; mt < 2; mt++)
#pragma unroll
            for (int h = 0; h < 2; h++) {
                int lr = mb + mt * 16 + g + h * 8;
                float s = redS[lr][0] + redS[lr][1] + redS[lr][2] + redS[lr][3];
                float q = redQ[lr][0] + redQ[lr][1] + redQ[lr][2] + redQ[lr][3];
                float m = s * (1.f / 256.f);
                float v = q * (1.f / 256.f) - m * m;
                mu[mt * 2 + h] = m;
                rstd[mt * 2 + h] = rsqrtf(v + 1e-5f);
            }
#pragma unroll
        for (int mt = 0; mt < 2; mt++)
#pragma unroll
            for (int nt = 0; nt < 8; nt++) {
                int j = nbo + nt * 8 + tg * 2;
                float2 gm = *(const float2*)(gamma + j);
                float2 bt = *(const float2*)(beta + j);
#pragma unroll
                for (int h = 0; h < 2; h++) {
                    int row = m0 + mb + mt * 16 + g + h * 8;
                    float m = mu[mt * 2 + h], r = rstd[mt * 2 + h];
                    float o0 = (acc[mt][nt][h * 2 + 0] - m) * r * gm.x + bt.x;
                    float o1 = (acc[mt][nt][h * 2 + 1] - m) * r * gm.y + bt.y;
                    *(float2*)(out + (size_t)row * 256 + j) = make_float2(o0, o1);
                }
            }
    }
}

// ---------------- neighbor gather + logits + softmax + gated context ------
__global__ __launch_bounds__(256, 1)
void neigh_kernel(const float* __restrict__ all_embs,
                  const int* __restrict__ nb_idx,
                  const float* __restrict__ nb_w) {
    const int warp = threadIdx.x >> 5;
    const int lane = threadIdx.x & 31;
    const int b = blockIdx.x * 8 + warp;

    int   myidx = 0;
    float mylw  = 0.f;
    if (lane < 16) {
        myidx = nb_idx[b * 16 + lane];
        mylw  = __logf(fmaxf(nb_w[b * 16 + lane], 1e-6f));
    }

    float4 nlo[16], nhi[16];
#pragma unroll
    for (int k = 0; k < 16; k++) {
        int r = __shfl_sync(0xffffffffu, myidx, k);
        const float4* rp = (const float4*)(all_embs + (size_t)r * 256);
        nlo[k] = rp[lane];
        nhi[k] = rp[32 + lane];
    }

    const float4* prow = (const float4*)(g_E + (size_t)b * 768);
    float4 plo = prow[lane], phi = prow[32 + lane];

    float logit[16];
#pragma unroll
    for (int k = 0; k < 16; k++) {
        float s = nlo[k].x * plo.x + nlo[k].y * plo.y + nlo[k].z * plo.z + nlo[k].w * plo.w
                + nhi[k].x * phi.x + nhi[k].y * phi.y + nhi[k].z * phi.z + nhi[k].w * phi.w;
        s = warp_sum(s);
        float lw = __shfl_sync(0xffffffffu, mylw, k);
        logit[k] = s * 0.125f + lw;   // SCALE = 64^-0.5
    }

    float mx = logit[0];
#pragma unroll
    for (int k = 1; k < 16; k++) mx = fmaxf(mx, logit[k]);
    float esum = 0.f;
#pragma unroll
    for (int k = 0; k < 16; k++) { logit[k] = __expf(logit[k] - mx); esum += logit[k]; }
    float inv = 1.f / esum;

    float4 clo = make_float4(0, 0, 0, 0), chi = make_float4(0, 0, 0, 0);
#pragma unroll
    for (int k = 0; k < 16; k++) {
        float a = logit[k] * inv;
        clo.x = fmaf(a, nlo[k].x, clo.x); clo.y = fmaf(a, nlo[k].y, clo.y);
        clo.z = fmaf(a, nlo[k].z, clo.z); clo.w = fmaf(a, nlo[k].w, clo.w);
        chi.x = fmaf(a, nhi[k].x, chi.x); chi.y = fmaf(a, nhi[k].y, chi.y);
        chi.z = fmaf(a, nhi[k].z, chi.z); chi.w = fmaf(a, nhi[k].w, chi.w);
    }

    const float4* grow = (const float4*)(g_E + (size_t)b * 768 + 256);
    float4 glo = grow[lane], ghi = grow[32 + lane];
    float4* crow = (float4*)(g_ctx + (size_t)b * 256);
    crow[lane]      = make_float4(glo.x * clo.x, glo.y * clo.y, glo.z * clo.z, glo.w * clo.w);
    crow[32 + lane] = make_float4(ghi.x * chi.x, ghi.y * chi.y, ghi.z * chi.z, ghi.w * chi.w);
}

// ---------------- launch ---------------------------------------------------
extern "C" void kernel_launch(void* const* d_in, const int* in_sizes, int n_in,
                              void* d_out, int out_size) {
    const float* all_embs   = (const float*)d_in[0];
    const int*   center_idx = (const int*)d_in[1];
    const int*   nb_idx     = (const int*)d_in[2];
    const float* nb_w       = (const float*)d_in[3];
    const float* Wq         = (const float*)d_in[4];
    const float* Wk         = (const float*)d_in[5];
    const float* Wg         = (const float*)d_in[6];
    const float* bg         = (const float*)d_in[7];
    const float* Wo         = (const float*)d_in[8];
    const float* bo         = (const float*)d_in[9];
    const float* gamma      = (const float*)d_in[10];
    const float* beta       = (const float*)d_in[11];
    float* out = (float*)d_out;

    const int sm0 = 3 * (128 + 192) * PITCH * 4;   // 138240
    const int sm1 = 3 * (128 + 256) * PITCH * 4;   // 165888
    const int sm2 = 2 * (128 + 256) * PITCH * 4;   // 110592

    static int configured = 0;
    if (!configured) {
        cudaFuncSetAttribute((const void*)gemm_kernel<0, 192, 8, 384>,
                             cudaFuncAttributeMaxDynamicSharedMemorySize, sm0);
        cudaFuncSetAttribute((const void*)gemm_kernel<1, 256, 8, 512>,
                             cudaFuncAttributeMaxDynamicSharedMemorySize, sm1);
        cudaFuncSetAttribute((const void*)gemm_kernel<2, 256, 2, 512>,
                             cudaFuncAttributeMaxDynamicSharedMemorySize, sm2);
        configured = 1;
    }

    prep_kernel<<<1088, 256>>>(Wq, Wk, Wg, Wo);
    gemm_kernel<0, 192, 8, 384><<<dim3(BATCH / 128, 3), 384, sm0>>>(
        all_embs, center_idx, bg, bo, gamma, beta, nullptr);
    gemm_kernel<2, 256, 2, 512><<<dim3(BATCH / 128, 1), 512, sm2>>>(
        all_embs, center_idx, bg, bo, gamma, beta, nullptr);
    neigh_kernel<<<BATCH / 8, 256>>>(all_embs, nb_idx, nb_w);
    gemm_kernel<1, 256, 8, 512><<<dim3(BATCH / 128, 1), 512, sm1>>>(
        all_embs, center_idx, bg, bo, gamma, beta, out);
}

// round 6
// speedup vs baseline: 1.0162x; 1.0162x over previous
#include <cuda_runtime.h>
#include <cstdint>

#define BATCH 32768
#define PITCH 36
#define A_WORDS (128 * PITCH)
#define B_WORDS (256 * PITCH)
#define STAGE_WORDS (A_WORDS + B_WORDS)

// ---------------- device scratch (static, allocation-free) ----------------
__device__ __align__(128) float g_W1[768 * 256];          // M^T | Wg | Wo1 (tf32-rounded)
__device__ __align__(128) float g_W2[256 * 256];          // Wo2 (tf32-rounded)
__device__ __align__(128) float g_E[(size_t)BATCH * 768]; // P | gate | E1
__device__ __align__(128) float g_ctx[(size_t)BATCH * 256];

__device__ __forceinline__ float rnd_tf32(float x) {
    uint32_t y;
    asm("cvt.rna.tf32.f32 %0, %1;" : "=r"(y) : "f"(x));
    return __uint_as_float(y);
}
__device__ __forceinline__ void cp_async16(void* smem_dst, const void* gmem_src) {
    uint32_t s = (uint32_t)__cvta_generic_to_shared(smem_dst);
    asm volatile("cp.async.cg.shared.global [%0], [%1], 16;\n" :: "r"(s), "l"(gmem_src));
}
__device__ __forceinline__ void ldsm_x4(uint32_t& r0, uint32_t& r1, uint32_t& r2, uint32_t& r3,
                                        uint32_t saddr) {
    asm volatile("ldmatrix.sync.aligned.m8n8.x4.shared.b16 {%0,%1,%2,%3}, [%4];"
                 : "=r"(r0), "=r"(r1), "=r"(r2), "=r"(r3) : "r"(saddr));
}
__device__ __forceinline__ float warp_sum(float v) {
    v += __shfl_xor_sync(0xffffffffu, v, 16);
    v += __shfl_xor_sync(0xffffffffu, v, 8);
    v += __shfl_xor_sync(0xffffffffu, v, 4);
    v += __shfl_xor_sync(0xffffffffu, v, 2);
    v += __shfl_xor_sync(0xffffffffu, v, 1);
    return v;
}

// ---------------- K0: build fused weight matrices --------------------------
__global__ void prep_kernel(const float* __restrict__ Wq, const float* __restrict__ Wk,
                            const float* __restrict__ Wg, const float* __restrict__ Wo) {
    int j = blockIdx.x;
    int e = threadIdx.x;
    if (j < 256) {
        float s = 0.f;
#pragma unroll 8
        for (int a = 0; a < 64; a++)
            s = fmaf(Wq[a * 256 + e], Wk[a * 256 + j], s);
        g_W1[j * 256 + e] = rnd_tf32(s);
    } else if (j < 512) {
        g_W1[j * 256 + e] = rnd_tf32(Wg[(j - 256) * 256 + e]);
    } else if (j < 768) {
        g_W1[j * 256 + e] = rnd_tf32(Wo[(j - 512) * 512 + e]);
    } else {
        g_W2[(j - 768) * 256 + e] = rnd_tf32(Wo[(j - 768) * 512 + 256 + e]);
    }
}

// ---------------- GEMM: tf32 mma.sync, 128x256 CTA tile, 2-stage cp.async --
template <int EPI>
__global__ __launch_bounds__(512, 1)
void gemm_kernel(const float* __restrict__ all_embs,
                 const int* __restrict__ center_idx,
                 const float* __restrict__ bg,
                 const float* __restrict__ bo,
                 const float* __restrict__ gamma,
                 const float* __restrict__ beta,
                 float* __restrict__ out) {
    extern __shared__ float sm[];
    __shared__ int   ridx[128];
    __shared__ float redS[128][4];
    __shared__ float redQ[128][4];

    const int t    = threadIdx.x;
    const int lane = t & 31;
    const int warp = t >> 5;
    const int m0 = blockIdx.x * 128;
    const int n0 = blockIdx.y * 256;
    const float* Bmat = (EPI == 0) ? g_W1 : g_W2;

    if (t < 128) ridx[t] = center_idx[m0 + t];
    __syncthreads();

    const uint32_t sm_u32 = (uint32_t)__cvta_generic_to_shared(sm);

    const int g   = lane >> 2;
    const int tg  = lane & 3;
    const int mb  = (warp & 3) * 32;
    const int nbo = (warp >> 2) * 64;

    uint32_t a_off[2], b_off[4];
#pragma unroll
    for (int mt = 0; mt < 2; mt++)
        a_off[mt] = ((mb + mt * 16 + (lane & 15)) * PITCH + ((lane >> 4) & 1) * 4) * 4;
#pragma unroll
    for (int p = 0; p < 4; p++)
        b_off[p] = (A_WORDS + (nbo + p * 16 + ((lane >> 4) & 1) * 8 + (lane & 7)) * PITCH
                    + ((lane >> 3) & 1) * 4) * 4;

    auto load_stage = [&](int kk, int s) {
        float* base = sm + s * STAGE_WORDS;
#pragma unroll
        for (int i = 0; i < 2; i++) {
            int idx = t + i * 512;
            int row = idx >> 3, ch = (idx & 7) * 4;
            const float* src = (EPI == 0)
                ? (all_embs + (size_t)ridx[row] * 256 + kk + ch)
                : (g_ctx + (size_t)(m0 + row) * 256 + kk + ch);
            cp_async16(base + row * PITCH + ch, src);
        }
#pragma unroll
        for (int i = 0; i < 4; i++) {
            int idx = t + i * 512;
            int row = idx >> 3, ch = (idx & 7) * 4;
            cp_async16(base + A_WORDS + row * PITCH + ch,
                       Bmat + (size_t)(n0 + row) * 256 + kk + ch);
        }
    };

    float acc[2][8][4] = {};

    load_stage(0, 0);
    asm volatile("cp.async.commit_group;\n" ::: "memory");

#pragma unroll 1
    for (int it = 0; it < 8; ++it) {
        const int s = it & 1;
        asm volatile("cp.async.wait_group 0;\n" ::: "memory");
        __syncthreads();
        if (it + 1 < 8) load_stage((it + 1) * 32, s ^ 1);
        asm volatile("cp.async.commit_group;\n" ::: "memory");

        const uint32_t stage = sm_u32 + s * (STAGE_WORDS * 4);
#pragma unroll
        for (int ks = 0; ks < 4; ks++) {
            const uint32_t kbyte = ks * 32;
            uint32_t a[2][4];
#pragma unroll
            for (int mt = 0; mt < 2; mt++)
                ldsm_x4(a[mt][0], a[mt][1], a[mt][2], a[mt][3], stage + a_off[mt] + kbyte);
            uint32_t bf[8][2];
#pragma unroll
            for (int p = 0; p < 4; p++)
                ldsm_x4(bf[2 * p][0], bf[2 * p][1], bf[2 * p + 1][0], bf[2 * p + 1][1],
                        stage + b_off[p] + kbyte);
#pragma unroll
            for (int mt = 0; mt < 2; mt++)
#pragma unroll
                for (int nt = 0; nt < 8; nt++)
                    asm volatile(
                        "mma.sync.aligned.m16n8k8.row.col.f32.tf32.tf32.f32 "
                        "{%0,%1,%2,%3}, {%4,%5,%6,%7}, {%8,%9}, {%0,%1,%2,%3};\n"
                        : "+f"(acc[mt][nt][0]), "+f"(acc[mt][nt][1]),
                          "+f"(acc[mt][nt][2]), "+f"(acc[mt][nt][3])
                        : "r"(a[mt][0]), "r"(a[mt][1]), "r"(a[mt][2]), "r"(a[mt][3]),
                          "r"(bf[nt][0]), "r"(bf[nt][1]));
        }
        __syncthreads();
    }

    if (EPI == 0) {
#pragma unroll
        for (int mt = 0; mt < 2; mt++)
#pragma unroll
            for (int nt = 0; nt < 8; nt++) {
                int lc = nbo + nt * 8 + tg * 2;
#pragma unroll
                for (int h = 0; h < 2; h++) {
                    int row = m0 + mb + mt * 16 + g + h * 8;
                    float v0 = acc[mt][nt][h * 2 + 0];
                    float v1 = acc[mt][nt][h * 2 + 1];
                    int j = n0 + lc;
                    if (j < 256) {
                        // P: raw
                    } else if (j < 512) {
                        v0 = 1.f / (1.f + __expf(-(v0 + bg[j - 256])));
                        v1 = 1.f / (1.f + __expf(-(v1 + bg[j - 255])));
                    } else {
                        v0 += bo[j - 512];
                        v1 += bo[j - 511];
                    }
                    *(float2*)(g_E + (size_t)row * 768 + j) = make_float2(v0, v1);
                }
            }
    } else {
        float rs[4] = {0.f, 0.f, 0.f, 0.f};
        float rq[4] = {0.f, 0.f, 0.f, 0.f};
#pragma unroll
        for (int mt = 0; mt < 2; mt++)
#pragma unroll
            for (int h = 0; h < 2; h++) {
                int lr = mb + mt * 16 + g + h * 8;
                int row = m0 + lr;
                const float* cen = all_embs + (size_t)ridx[lr] * 256;
                const float* e1r = g_E + (size_t)row * 768 + 512;
                float s = 0.f, q = 0.f;
#pragma unroll
                for (int nt = 0; nt < 8; nt++) {
                    int j = nbo + nt * 8 + tg * 2;
                    float2 e1 = *(const float2*)(e1r + j);
                    float2 c2 = *(const float2*)(cen + j);
                    float v0 = acc[mt][nt][h * 2 + 0] + e1.x + c2.x;
                    float v1 = acc[mt][nt][h * 2 + 1] + e1.y + c2.y;
                    acc[mt][nt][h * 2 + 0] = v0;
                    acc[mt][nt][h * 2 + 1] = v1;
                    s += v0 + v1;
                    q += v0 * v0 + v1 * v1;
                }
                rs[mt * 2 + h] = s;
                rq[mt * 2 + h] = q;
            }
#pragma unroll
        for (int i = 0; i < 4; i++) {
            rs[i] += __shfl_xor_sync(0xffffffffu, rs[i], 1);
            rs[i] += __shfl_xor_sync(0xffffffffu, rs[i], 2);
            rq[i] += __shfl_xor_sync(0xffffffffu, rq[i], 1);
            rq[i] += __shfl_xor_sync(0xffffffffu, rq[i], 2);
        }
        const int nw = warp >> 2;
        if (tg == 0) {
#pragma unroll
            for (int mt = 0; mt < 2; mt++)
#pragma unroll
                for (int h = 0; h < 2; h++) {
                    int lr = mb + mt * 16 + g + h * 8;
                    redS[lr][nw] = rs[mt * 2 + h];
                    redQ[lr][nw] = rq[mt * 2 + h];
                }
        }
        __syncthreads();
        float mu[4], rstd[4];
#pragma unroll
        for (int mt = 0; mt < 2; mt++)
#pragma unroll
            for (int h = 0; h < 2; h++) {
                int lr = mb + mt * 16 + g + h * 8;
                float s = redS[lr][0] + redS[lr][1] + redS[lr][2] + redS[lr][3];
                float q = redQ[lr][0] + redQ[lr][1] + redQ[lr][2] + redQ[lr][3];
                float m = s * (1.f / 256.f);
                float v = q * (1.f / 256.f) - m * m;
                mu[mt * 2 + h] = m;
                rstd[mt * 2 + h] = rsqrtf(v + 1e-5f);
            }
#pragma unroll
        for (int mt = 0; mt < 2; mt++)
#pragma unroll
            for (int nt = 0; nt < 8; nt++) {
                int j = nbo + nt * 8 + tg * 2;
                float2 gm = *(const float2*)(gamma + j);
                float2 bt = *(const float2*)(beta + j);
#pragma unroll
                for (int h = 0; h < 2; h++) {
                    int row = m0 + mb + mt * 16 + g + h * 8;
                    float m = mu[mt * 2 + h], r = rstd[mt * 2 + h];
                    float o0 = (acc[mt][nt][h * 2 + 0] - m) * r * gm.x + bt.x;
                    float o1 = (acc[mt][nt][h * 2 + 1] - m) * r * gm.y + bt.y;
                    *(float2*)(out + (size_t)row * 256 + j) = make_float2(o0, o1);
                }
            }
    }
}

// ---------------- neigh: 4 warps per row, 2 rows per 256-thread CTA --------
// Each warp caches 4 neighbors (32 regs); softmax exchanged via smem; partial
// contexts combined by staged smem reduction under named barriers per row-group.
__global__ __launch_bounds__(256, 3)
void neigh_kernel(const float* __restrict__ all_embs,
                  const int* __restrict__ nb_idx,
                  const float* __restrict__ nb_w) {
    __shared__ float sL[2][16];
    __shared__ float sW[2][16];
    __shared__ float4 ctxbuf[2][2][64];

    const int t    = threadIdx.x;
    const int lane = t & 31;
    const int warp = t >> 5;
    const int wg   = warp >> 2;           // row group 0/1
    const int sub  = warp & 3;            // neighbor quarter
    const int b    = blockIdx.x * 2 + wg;
    const int barid = 1 + wg;

    int   myidx = 0;
    float myw   = 0.f;
    if (lane < 4) {
        myidx = nb_idx[b * 16 + sub * 4 + lane];
        myw   = fmaxf(nb_w[b * 16 + sub * 4 + lane], 1e-6f);
    }

    // cache this warp's 4 neighbor rows
    float4 nlo[4], nhi[4];
#pragma unroll
    for (int k = 0; k < 4; k++) {
        int r = __shfl_sync(0xffffffffu, myidx, k);
        const float4* rp = (const float4*)(all_embs + (size_t)r * 256);
        nlo[k] = rp[lane];
        nhi[k] = rp[32 + lane];
    }

    const float4* prow = (const float4*)(g_E + (size_t)b * 768);
    float4 plo = prow[lane], phi = prow[32 + lane];

    // 4 dot products (all lanes end with the value)
    float lg[4];
#pragma unroll
    for (int k = 0; k < 4; k++) {
        float s = nlo[k].x * plo.x + nlo[k].y * plo.y + nlo[k].z * plo.z + nlo[k].w * plo.w
                + nhi[k].x * phi.x + nhi[k].y * phi.y + nhi[k].z * phi.z + nhi[k].w * phi.w;
        lg[k] = warp_sum(s) * 0.125f;     // SCALE = 64^-0.5
    }
    if (lane < 4) {
        sL[wg][sub * 4 + lane] = lg[lane];
        sW[wg][sub * 4 + lane] = myw;
    }
    asm volatile("bar.sync %0, 128;" :: "r"(barid) : "memory");

    // softmax over 16 (weights folded in: w * exp(l - max l)), redundant per warp
    float l = (lane < 16) ? sL[wg][lane] : -1e30f;
    float w = (lane < 16) ? sW[wg][lane] : 0.f;
    float mx = l;
#pragma unroll
    for (int off = 8; off >= 1; off >>= 1) mx = fmaxf(mx, __shfl_xor_sync(0xffffffffu, mx, off));
    float e = (lane < 16) ? w * __expf(l - mx) : 0.f;
    float es = e;
#pragma unroll
    for (int off = 8; off >= 1; off >>= 1) es += __shfl_xor_sync(0xffffffffu, es, off);
    float ai = e * (1.f / es);
    float a[4];
#pragma unroll
    for (int k = 0; k < 4; k++) a[k] = __shfl_sync(0xffffffffu, ai, sub * 4 + k);

    // partial context over this warp's 4 neighbors
    float4 clo = make_float4(0, 0, 0, 0), chi = make_float4(0, 0, 0, 0);
#pragma unroll
    for (int k = 0; k < 4; k++) {
        clo.x = fmaf(a[k], nlo[k].x, clo.x); clo.y = fmaf(a[k], nlo[k].y, clo.y);
        clo.z = fmaf(a[k], nlo[k].z, clo.z); clo.w = fmaf(a[k], nlo[k].w, clo.w);
        chi.x = fmaf(a[k], nhi[k].x, chi.x); chi.y = fmaf(a[k], nhi[k].y, chi.y);
        chi.z = fmaf(a[k], nhi[k].z, chi.z); chi.w = fmaf(a[k], nhi[k].w, chi.w);
    }

    // staged cross-warp reduction (4 -> 2 -> 1)
    if (sub >= 2) {
        ctxbuf[wg][sub - 2][lane]      = clo;
        ctxbuf[wg][sub - 2][32 + lane] = chi;
    }
    asm volatile("bar.sync %0, 128;" :: "r"(barid) : "memory");
    if (sub < 2) {
        float4 o0 = ctxbuf[wg][sub][lane];
        float4 o1 = ctxbuf[wg][sub][32 + lane];
        clo.x += o0.x; clo.y += o0.y; clo.z += o0.z; clo.w += o0.w;
        chi.x += o1.x; chi.y += o1.y; chi.z += o1.z; chi.w += o1.w;
    }
    asm volatile("bar.sync %0, 128;" :: "r"(barid) : "memory");
    if (sub == 1) {
        ctxbuf[wg][0][lane]      = clo;
        ctxbuf[wg][0][32 + lane] = chi;
    }
    asm volatile("bar.sync %0, 128;" :: "r"(barid) : "memory");
    if (sub == 0) {
        float4 o0 = ctxbuf[wg][0][lane];
        float4 o1 = ctxbuf[wg][0][32 + lane];
        clo.x += o0.x; clo.y += o0.y; clo.z += o0.z; clo.w += o0.w;
        chi.x += o1.x; chi.y += o1.y; chi.z += o1.z; chi.w += o1.w;
        const float4* grow = (const float4*)(g_E + (size_t)b * 768 + 256);
        float4 glo = grow[lane], ghi = grow[32 + lane];
        float4* crow = (float4*)(g_ctx + (size_t)b * 256);
        crow[lane]      = make_float4(glo.x * clo.x, glo.y * clo.y, glo.z * clo.z, glo.w * clo.w);
        crow[32 + lane] = make_float4(ghi.x * chi.x, ghi.y * chi.y, ghi.z * chi.z, ghi.w * chi.w);
    }
}

// ---------------- launch ---------------------------------------------------
extern "C" void kernel_launch(void* const* d_in, const int* in_sizes, int n_in,
                              void* d_out, int out_size) {
    const float* all_embs   = (const float*)d_in[0];
    const int*   center_idx = (const int*)d_in[1];
    const int*   nb_idx     = (const int*)d_in[2];
    const float* nb_w       = (const float*)d_in[3];
    const float* Wq         = (const float*)d_in[4];
    const float* Wk         = (const float*)d_in[5];
    const float* Wg         = (const float*)d_in[6];
    const float* bg         = (const float*)d_in[7];
    const float* Wo         = (const float*)d_in[8];
    const float* bo         = (const float*)d_in[9];
    const float* gamma      = (const float*)d_in[10];
    const float* beta       = (const float*)d_in[11];
    float* out = (float*)d_out;

    const int smem_bytes = 2 * STAGE_WORDS * sizeof(float);   // 110592
    static int configured = 0;
    if (!configured) {
        cudaFuncSetAttribute(gemm_kernel<0>, cudaFuncAttributeMaxDynamicSharedMemorySize, smem_bytes);
        cudaFuncSetAttribute(gemm_kernel<1>, cudaFuncAttributeMaxDynamicSharedMemorySize, smem_bytes);
        configured = 1;
    }

    prep_kernel<<<1024, 256>>>(Wq, Wk, Wg, Wo);
    gemm_kernel<0><<<dim3(BATCH / 128, 3), 512, smem_bytes>>>(all_embs, center_idx, bg, bo, gamma, beta, nullptr);
    neigh_kernel<<<BATCH / 2, 256>>>(all_embs, nb_idx, nb_w);
    gemm_kernel<1><<<dim3(BATCH / 128, 1), 512, smem_bytes>>>(all_embs, center_idx, bg, bo, gamma, beta, out);
}

// round 7
// speedup vs baseline: 1.3183x; 1.2972x over previous
#include <cuda_runtime.h>
#include <cstdint>

#define BATCH 32768
#define NEMB  20000
#define PITCH 36
#define A_WORDS (128 * PITCH)

// ---------------- device scratch (static, allocation-free) ----------------
__device__ __align__(128) float g_W1[512 * 256];           // Wg(256) | Wo1(256), tf32-rounded
__device__ __align__(128) float g_W2[256 * 256];           // Wo2
__device__ __align__(128) float g_Wq[64 * 256];            // Wq rows (tf32)
__device__ __align__(128) float g_Wk[64 * 256];            // Wk rows (tf32)
__device__ __align__(128) float g_q[(size_t)BATCH * 64];   // q = C Wq^T
__device__ __align__(128) float g_ke[(size_t)NEMB * 64];   // ke = E Wk^T
__device__ __align__(128) float g_E[(size_t)BATCH * 512];  // gate | E1
__device__ __align__(128) float g_ctx[(size_t)BATCH * 256];

__device__ __forceinline__ float rnd_tf32(float x) {
    uint32_t y;
    asm("cvt.rna.tf32.f32 %0, %1;" : "=r"(y) : "f"(x));
    return __uint_as_float(y);
}
__device__ __forceinline__ void cp_async16(void* smem_dst, const void* gmem_src) {
    uint32_t s = (uint32_t)__cvta_generic_to_shared(smem_dst);
    asm volatile("cp.async.cg.shared.global [%0], [%1], 16;\n" :: "r"(s), "l"(gmem_src));
}
__device__ __forceinline__ void ldsm_x4(uint32_t& r0, uint32_t& r1, uint32_t& r2, uint32_t& r3,
                                        uint32_t saddr) {
    asm volatile("ldmatrix.sync.aligned.m8n8.x4.shared.b16 {%0,%1,%2,%3}, [%4];"
                 : "=r"(r0), "=r"(r1), "=r"(r2), "=r"(r3) : "r"(saddr));
}
__device__ __forceinline__ float warp_sum(float v) {
    v += __shfl_xor_sync(0xffffffffu, v, 16);
    v += __shfl_xor_sync(0xffffffffu, v, 8);
    v += __shfl_xor_sync(0xffffffffu, v, 4);
    v += __shfl_xor_sync(0xffffffffu, v, 2);
    v += __shfl_xor_sync(0xffffffffu, v, 1);
    return v;
}

// ---------------- K0: tf32-rounded weight copies ---------------------------
__global__ void prep_kernel(const float* __restrict__ Wq, const float* __restrict__ Wk,
                            const float* __restrict__ Wg, const float* __restrict__ Wo) {
    int j = blockIdx.x;
    int e = threadIdx.x;
    if (j < 256)       g_W1[j * 256 + e] = rnd_tf32(Wg[j * 256 + e]);
    else if (j < 512)  g_W1[j * 256 + e] = rnd_tf32(Wo[(j - 256) * 512 + e]);
    else if (j < 768)  g_W2[(j - 512) * 256 + e] = rnd_tf32(Wo[(j - 512) * 512 + 256 + e]);
    else if (j < 832)  g_Wq[(j - 768) * 256 + e] = rnd_tf32(Wq[(j - 768) * 256 + e]);
    else               g_Wk[(j - 832) * 256 + e] = rnd_tf32(Wk[(j - 832) * 256 + e]);
}

// ---------------- GEMM template (tf32 mma.sync, 2-stage cp.async) ----------
// MODE 0: A=gathered centers, B=g_W1 slab,  128x128 tile -> gate|E1
// MODE 1: A=g_ctx,            B=g_W2,       128x256 tile -> +E1+center, LN -> out
// MODE 2: A=gathered centers, B=g_Wq (64),  128x64 tile  -> g_q
// MODE 3: A=all_embs rows,    B=g_Wk (64),  128x64 tile  -> g_ke (guarded)
template <int MODE, int BROWS, int NTH>
__global__ __launch_bounds__(NTH, (NTH == 512) ? 1 : 2)
void gemm_kernel(const float* __restrict__ all_embs,
                 const int* __restrict__ center_idx,
                 const float* __restrict__ bg,
                 const float* __restrict__ bo,
                 const float* __restrict__ gamma,
                 const float* __restrict__ beta,
                 float* __restrict__ out) {
    constexpr int STAGE_WORDS = (128 + BROWS) * PITCH;
    extern __shared__ float sm[];
    __shared__ int   ridx[128];
    __shared__ float redS[128][4];
    __shared__ float redQ[128][4];

    const int t    = threadIdx.x;
    const int lane = t & 31;
    const int warp = t >> 5;
    const int m0 = blockIdx.x * 128;
    const int n0 = blockIdx.y * BROWS;
    const float* Bmat;
    if (MODE == 0)      Bmat = g_W1 + (size_t)n0 * 256;
    else if (MODE == 1) Bmat = g_W2;
    else if (MODE == 2) Bmat = g_Wq;
    else                Bmat = g_Wk;

    if ((MODE == 0 || MODE == 1 || MODE == 2) && t < 128) ridx[t] = center_idx[m0 + t];
    __syncthreads();

    const uint32_t sm_u32 = (uint32_t)__cvta_generic_to_shared(sm);
    const int g   = lane >> 2;
    const int tg  = lane & 3;
    const int mb  = (warp & 3) * 32;
    const int nbo = (warp >> 2) * 64;

    uint32_t a_off[2], b_off[4];
#pragma unroll
    for (int mt = 0; mt < 2; mt++)
        a_off[mt] = ((mb + mt * 16 + (lane & 15)) * PITCH + ((lane >> 4) & 1) * 4) * 4;
#pragma unroll
    for (int p = 0; p < 4; p++)
        b_off[p] = (A_WORDS + (nbo + p * 16 + ((lane >> 4) & 1) * 8 + (lane & 7)) * PITCH
                    + ((lane >> 3) & 1) * 4) * 4;

    auto load_stage = [&](int kk, int s) {
        float* base = sm + s * STAGE_WORDS;
        for (int idx = t; idx < 128 * 8; idx += NTH) {
            int row = idx >> 3, ch = (idx & 7) * 4;
            const float* src;
            if (MODE == 0 || MODE == 2)
                src = all_embs + (size_t)ridx[row] * 256 + kk + ch;
            else if (MODE == 1)
                src = g_ctx + (size_t)(m0 + row) * 256 + kk + ch;
            else {
                int r = m0 + row; if (r >= NEMB) r = NEMB - 1;
                src = all_embs + (size_t)r * 256 + kk + ch;
            }
            cp_async16(base + row * PITCH + ch, src);
        }
        for (int idx = t; idx < BROWS * 8; idx += NTH) {
            int row = idx >> 3, ch = (idx & 7) * 4;
            cp_async16(base + A_WORDS + row * PITCH + ch,
                       Bmat + (size_t)row * 256 + kk + ch);
        }
    };

    float acc[2][8][4] = {};

    load_stage(0, 0);
    asm volatile("cp.async.commit_group;\n" ::: "memory");

#pragma unroll 1
    for (int it = 0; it < 8; ++it) {
        const int s = it & 1;
        asm volatile("cp.async.wait_group 0;\n" ::: "memory");
        __syncthreads();
        if (it + 1 < 8) load_stage((it + 1) * 32, s ^ 1);
        asm volatile("cp.async.commit_group;\n" ::: "memory");

        const uint32_t stage = sm_u32 + s * (STAGE_WORDS * 4);
#pragma unroll
        for (int ks = 0; ks < 4; ks++) {
            const uint32_t kbyte = ks * 32;
            uint32_t a[2][4];
#pragma unroll
            for (int mt = 0; mt < 2; mt++)
                ldsm_x4(a[mt][0], a[mt][1], a[mt][2], a[mt][3], stage + a_off[mt] + kbyte);
            uint32_t bf[8][2];
#pragma unroll
            for (int p = 0; p < 4; p++)
                ldsm_x4(bf[2 * p][0], bf[2 * p][1], bf[2 * p + 1][0], bf[2 * p + 1][1],
                        stage + b_off[p] + kbyte);
#pragma unroll
            for (int mt = 0; mt < 2; mt++)
#pragma unroll
                for (int nt = 0; nt < 8; nt++)
                    asm volatile(
                        "mma.sync.aligned.m16n8k8.row.col.f32.tf32.tf32.f32 "
                        "{%0,%1,%2,%3}, {%4,%5,%6,%7}, {%8,%9}, {%0,%1,%2,%3};\n"
                        : "+f"(acc[mt][nt][0]), "+f"(acc[mt][nt][1]),
                          "+f"(acc[mt][nt][2]), "+f"(acc[mt][nt][3])
                        : "r"(a[mt][0]), "r"(a[mt][1]), "r"(a[mt][2]), "r"(a[mt][3]),
                          "r"(bf[nt][0]), "r"(bf[nt][1]));
        }
        __syncthreads();
    }

    if (MODE == 0) {
#pragma unroll
        for (int mt = 0; mt < 2; mt++)
#pragma unroll
            for (int nt = 0; nt < 8; nt++) {
                int j = n0 + nbo + nt * 8 + tg * 2;   // [0,512)
#pragma unroll
                for (int h = 0; h < 2; h++) {
                    int row = m0 + mb + mt * 16 + g + h * 8;
                    float v0 = acc[mt][nt][h * 2 + 0];
                    float v1 = acc[mt][nt][h * 2 + 1];
                    if (j < 256) {
                        v0 = 1.f / (1.f + __expf(-(v0 + bg[j])));
                        v1 = 1.f / (1.f + __expf(-(v1 + bg[j + 1])));
                    } else {
                        v0 += bo[j - 256];
                        v1 += bo[j - 255];
                    }
                    *(float2*)(g_E + (size_t)row * 512 + j) = make_float2(v0, v1);
                }
            }
    } else if (MODE == 2 || MODE == 3) {
#pragma unroll
        for (int mt = 0; mt < 2; mt++)
#pragma unroll
            for (int nt = 0; nt < 8; nt++) {
                int j = nt * 8 + tg * 2;              // [0,64)
#pragma unroll
                for (int h = 0; h < 2; h++) {
                    int row = m0 + mb + mt * 16 + g + h * 8;
                    float2 v = make_float2(acc[mt][nt][h * 2 + 0], acc[mt][nt][h * 2 + 1]);
                    if (MODE == 2)
                        *(float2*)(g_q + (size_t)row * 64 + j) = v;
                    else if (row < NEMB)
                        *(float2*)(g_ke + (size_t)row * 64 + j) = v;
                }
            }
    } else {
        // MODE 1: + E1 + center, fused LayerNorm
        float rs[4] = {0.f, 0.f, 0.f, 0.f};
        float rq[4] = {0.f, 0.f, 0.f, 0.f};
#pragma unroll
        for (int mt = 0; mt < 2; mt++)
#pragma unroll
            for (int h = 0; h < 2; h++) {
                int lr = mb + mt * 16 + g + h * 8;
                int row = m0 + lr;
                const float* cen = all_embs + (size_t)ridx[lr] * 256;
                const float* e1r = g_E + (size_t)row * 512 + 256;
                float s = 0.f, q = 0.f;
#pragma unroll
                for (int nt = 0; nt < 8; nt++) {
                    int j = nbo + nt * 8 + tg * 2;
                    float2 e1 = *(const float2*)(e1r + j);
                    float2 c2 = *(const float2*)(cen + j);
                    float v0 = acc[mt][nt][h * 2 + 0] + e1.x + c2.x;
                    float v1 = acc[mt][nt][h * 2 + 1] + e1.y + c2.y;
                    acc[mt][nt][h * 2 + 0] = v0;
                    acc[mt][nt][h * 2 + 1] = v1;
                    s += v0 + v1;
                    q += v0 * v0 + v1 * v1;
                }
                rs[mt * 2 + h] = s;
                rq[mt * 2 + h] = q;
            }
#pragma unroll
        for (int i = 0; i < 4; i++) {
            rs[i] += __shfl_xor_sync(0xffffffffu, rs[i], 1);
            rs[i] += __shfl_xor_sync(0xffffffffu, rs[i], 2);
            rq[i] += __shfl_xor_sync(0xffffffffu, rq[i], 1);
            rq[i] += __shfl_xor_sync(0xffffffffu, rq[i], 2);
        }
        const int nw = warp >> 2;
        if (tg == 0) {
#pragma unroll
            for (int mt = 0; mt < 2; mt++)
#pragma unroll
                for (int h = 0; h < 2; h++) {
                    int lr = mb + mt * 16 + g + h * 8;
                    redS[lr][nw] = rs[mt * 2 + h];
                    redQ[lr][nw] = rq[mt * 2 + h];
                }
        }
        __syncthreads();
        float mu[4], rstd[4];
#pragma unroll
        for (int mt = 0; mt < 2; mt++)
#pragma unroll
            for (int h = 0; h < 2; h++) {
                int lr = mb + mt * 16 + g + h * 8;
                float s = redS[lr][0] + redS[lr][1] + redS[lr][2] + redS[lr][3];
                float q = redQ[lr][0] + redQ[lr][1] + redQ[lr][2] + redQ[lr][3];
                float m = s * (1.f / 256.f);
                float v = q * (1.f / 256.f) - m * m;
                mu[mt * 2 + h] = m;
                rstd[mt * 2 + h] = rsqrtf(v + 1e-5f);
            }
#pragma unroll
        for (int mt = 0; mt < 2; mt++)
#pragma unroll
            for (int nt = 0; nt < 8; nt++) {
                int j = nbo + nt * 8 + tg * 2;
                float2 gm = *(const float2*)(gamma + j);
                float2 bt = *(const float2*)(beta + j);
#pragma unroll
                for (int h = 0; h < 2; h++) {
                    int row = m0 + mb + mt * 16 + g + h * 8;
                    float m = mu[mt * 2 + h], r = rstd[mt * 2 + h];
                    float o0 = (acc[mt][nt][h * 2 + 0] - m) * r * gm.x + bt.x;
                    float o1 = (acc[mt][nt][h * 2 + 1] - m) * r * gm.y + bt.y;
                    *(float2*)(out + (size_t)row * 256 + j) = make_float2(o0, o1);
                }
            }
    }
}

// ---------------- neigh v3: streaming, one warp per row --------------------
// logits from q . ke gather (256B/neighbor); rows streamed ONCE for context.
__global__ __launch_bounds__(256)
void neigh_kernel(const float* __restrict__ all_embs,
                  const int* __restrict__ nb_idx,
                  const float* __restrict__ nb_w) {
    const int warp = threadIdx.x >> 5;
    const int lane = threadIdx.x & 31;
    const int b = blockIdx.x * 8 + warp;

    const float q0 = g_q[(size_t)b * 64 + lane];
    const float q1 = g_q[(size_t)b * 64 + 32 + lane];

    int   myidx = 0;
    float myw   = 0.f;
    if (lane < 16) {
        myidx = nb_idx[b * 16 + lane];
        myw   = fmaxf(nb_w[b * 16 + lane], 1e-6f);
    }

    // logits: lane j keeps logit for neighbor j (j<16)
    float lgj = 0.f;
#pragma unroll
    for (int k = 0; k < 16; k++) {
        int r = __shfl_sync(0xffffffffu, myidx, k);
        const float* kp = g_ke + (size_t)r * 64;
        float s = warp_sum(kp[lane] * q0 + kp[32 + lane] * q1);
        if (lane == k) lgj = s;
    }

    // softmax over 16 lanes (weights folded: w * exp(l - max))
    float l = (lane < 16) ? lgj * 0.125f : -1e30f;
    float mx = l;
#pragma unroll
    for (int off = 8; off >= 1; off >>= 1)
        mx = fmaxf(mx, __shfl_xor_sync(0xffffffffu, mx, off));
    float e = (lane < 16) ? myw * __expf(l - mx) : 0.f;
    float es = e;
#pragma unroll
    for (int off = 8; off >= 1; off >>= 1)
        es += __shfl_xor_sync(0xffffffffu, es, off);
    float ai = e / es;

    // context: stream neighbor rows once
    float4 a0 = make_float4(0, 0, 0, 0), a1 = make_float4(0, 0, 0, 0);
#pragma unroll
    for (int k = 0; k < 16; k++) {
        int   r  = __shfl_sync(0xffffffffu, myidx, k);
        float ak = __shfl_sync(0xffffffffu, ai, k);
        const float4* rp = (const float4*)(all_embs + (size_t)r * 256);
        float4 f0 = rp[lane], f1 = rp[32 + lane];
        a0.x = fmaf(ak, f0.x, a0.x); a0.y = fmaf(ak, f0.y, a0.y);
        a0.z = fmaf(ak, f0.z, a0.z); a0.w = fmaf(ak, f0.w, a0.w);
        a1.x = fmaf(ak, f1.x, a1.x); a1.y = fmaf(ak, f1.y, a1.y);
        a1.z = fmaf(ak, f1.z, a1.z); a1.w = fmaf(ak, f1.w, a1.w);
    }

    const float4* gp = (const float4*)(g_E + (size_t)b * 512);
    float4 g0 = gp[lane], g1 = gp[32 + lane];
    float4* crow = (float4*)(g_ctx + (size_t)b * 256);
    crow[lane]      = make_float4(g0.x * a0.x, g0.y * a0.y, g0.z * a0.z, g0.w * a0.w);
    crow[32 + lane] = make_float4(g1.x * a1.x, g1.y * a1.y, g1.z * a1.z, g1.w * a1.w);
}

// ---------------- launch ---------------------------------------------------
extern "C" void kernel_launch(void* const* d_in, const int* in_sizes, int n_in,
                              void* d_out, int out_size) {
    const float* all_embs   = (const float*)d_in[0];
    const int*   center_idx = (const int*)d_in[1];
    const int*   nb_idx     = (const int*)d_in[2];
    const float* nb_w       = (const float*)d_in[3];
    const float* Wq         = (const float*)d_in[4];
    const float* Wk         = (const float*)d_in[5];
    const float* Wg         = (const float*)d_in[6];
    const float* bg         = (const float*)d_in[7];
    const float* Wo         = (const float*)d_in[8];
    const float* bo         = (const float*)d_in[9];
    const float* gamma      = (const float*)d_in[10];
    const float* beta       = (const float*)d_in[11];
    float* out = (float*)d_out;

    const int sm64  = 2 * (128 + 64) * PITCH * 4;    // 55296
    const int sm128 = 2 * (128 + 128) * PITCH * 4;   // 73728
    const int sm256 = 2 * (128 + 256) * PITCH * 4;   // 110592

    static int configured = 0;
    if (!configured) {
        cudaFuncSetAttribute((const void*)gemm_kernel<0, 128, 256>,
                             cudaFuncAttributeMaxDynamicSharedMemorySize, sm128);
        cudaFuncSetAttribute((const void*)gemm_kernel<1, 256, 512>,
                             cudaFuncAttributeMaxDynamicSharedMemorySize, sm256);
        cudaFuncSetAttribute((const void*)gemm_kernel<2, 64, 128>,
                             cudaFuncAttributeMaxDynamicSharedMemorySize, sm64);
        cudaFuncSetAttribute((const void*)gemm_kernel<3, 64, 128>,
                             cudaFuncAttributeMaxDynamicSharedMemorySize, sm64);
        configured = 1;
    }

    prep_kernel<<<896, 256>>>(Wq, Wk, Wg, Wo);
    gemm_kernel<2, 64, 128><<<dim3(BATCH / 128, 1), 128, sm64>>>(
        all_embs, center_idx, bg, bo, gamma, beta, nullptr);                     // q
    gemm_kernel<3, 64, 128><<<dim3((NEMB + 127) / 128, 1), 128, sm64>>>(
        all_embs, center_idx, bg, bo, gamma, beta, nullptr);                     // ke
    gemm_kernel<0, 128, 256><<<dim3(BATCH / 128, 4), 256, sm128>>>(
        all_embs, center_idx, bg, bo, gamma, beta, nullptr);                     // gate|E1
    neigh_kernel<<<BATCH / 8, 256>>>(all_embs, nb_idx, nb_w);
    gemm_kernel<1, 256, 512><<<dim3(BATCH / 128, 1), 512, sm256>>>(
        all_embs, center_idx, bg, bo, gamma, beta, out);                         // out + LN
}

// round 8
// speedup vs baseline: 1.6727x; 1.2688x over previous
#include <cuda_runtime.h>
#include <cstdint>

#define BATCH 32768
#define NEMB  20000
#define PITCH 36
#define A_WORDS (128 * PITCH)

// ---------------- device scratch (static, allocation-free) ----------------
__device__ __align__(128) float g_WT[640 * 256];            // Wq|Wk|Wg|Wo1 rows, tf32-rounded
__device__ __align__(128) float g_W2[256 * 256];            // Wo2, tf32-rounded
__device__ __align__(128) float g_T[(size_t)NEMB * 640];    // per-table-row: q(64)|ke(64)|gate(256)|E1(256)
__device__ __align__(128) float g_ctx[(size_t)BATCH * 256]; // gated context

__device__ __forceinline__ float rnd_tf32(float x) {
    uint32_t y;
    asm("cvt.rna.tf32.f32 %0, %1;" : "=r"(y) : "f"(x));
    return __uint_as_float(y);
}
__device__ __forceinline__ void cp_async16(void* smem_dst, const void* gmem_src) {
    uint32_t s = (uint32_t)__cvta_generic_to_shared(smem_dst);
    asm volatile("cp.async.cg.shared.global [%0], [%1], 16;\n" :: "r"(s), "l"(gmem_src));
}
__device__ __forceinline__ void ldsm_x4(uint32_t& r0, uint32_t& r1, uint32_t& r2, uint32_t& r3,
                                        uint32_t saddr) {
    asm volatile("ldmatrix.sync.aligned.m8n8.x4.shared.b16 {%0,%1,%2,%3}, [%4];"
                 : "=r"(r0), "=r"(r1), "=r"(r2), "=r"(r3) : "r"(saddr));
}
__device__ __forceinline__ float warp_sum(float v) {
    v += __shfl_xor_sync(0xffffffffu, v, 16);
    v += __shfl_xor_sync(0xffffffffu, v, 8);
    v += __shfl_xor_sync(0xffffffffu, v, 4);
    v += __shfl_xor_sync(0xffffffffu, v, 2);
    v += __shfl_xor_sync(0xffffffffu, v, 1);
    return v;
}

// ---------------- K0: tf32-rounded weight assembly -------------------------
__global__ void prep_kernel(const float* __restrict__ Wq, const float* __restrict__ Wk,
                            const float* __restrict__ Wg, const float* __restrict__ Wo) {
    int j = blockIdx.x;
    int e = threadIdx.x;
    if (j < 64)        g_WT[j * 256 + e] = rnd_tf32(Wq[j * 256 + e]);
    else if (j < 128)  g_WT[j * 256 + e] = rnd_tf32(Wk[(j - 64) * 256 + e]);
    else if (j < 384)  g_WT[j * 256 + e] = rnd_tf32(Wg[(j - 128) * 256 + e]);
    else if (j < 640)  g_WT[j * 256 + e] = rnd_tf32(Wo[(j - 384) * 512 + e]);
    else               g_W2[(j - 640) * 256 + e] = rnd_tf32(Wo[(j - 640) * 512 + 256 + e]);
}

// ---------------- GEMM template (tf32 mma.sync, 2-stage cp.async) ----------
// MODE 0: table transform. A = all_embs rows (contiguous), B = g_WT slab (128),
//         128x128 tile, 256 thr, 2 CTA/SM. Epilogue by region -> g_T.
// MODE 1: A = g_ctx, B = g_W2, 128x256 tile, 512 thr.
//         Epilogue: + E1(table) + center, fused LayerNorm -> out.
template <int MODE, int BROWS, int NTH>
__global__ __launch_bounds__(NTH, (NTH == 512) ? 1 : 2)
void gemm_kernel(const float* __restrict__ all_embs,
                 const int* __restrict__ center_idx,
                 const float* __restrict__ bg,
                 const float* __restrict__ bo,
                 const float* __restrict__ gamma,
                 const float* __restrict__ beta,
                 float* __restrict__ out) {
    constexpr int STAGE_WORDS = (128 + BROWS) * PITCH;
    extern __shared__ float sm[];
    __shared__ int   ridx[128];
    __shared__ float redS[128][4];
    __shared__ float redQ[128][4];

    const int t    = threadIdx.x;
    const int lane = t & 31;
    const int warp = t >> 5;
    const int m0 = blockIdx.x * 128;
    const int n0 = blockIdx.y * BROWS;
    const float* Bmat = (MODE == 0) ? (g_WT + (size_t)n0 * 256) : g_W2;

    if (MODE == 1 && t < 128) ridx[t] = center_idx[m0 + t];
    __syncthreads();

    const uint32_t sm_u32 = (uint32_t)__cvta_generic_to_shared(sm);
    const int g   = lane >> 2;
    const int tg  = lane & 3;
    const int mb  = (warp & 3) * 32;
    const int nbo = (warp >> 2) * 64;

    uint32_t a_off[2], b_off[4];
#pragma unroll
    for (int mt = 0; mt < 2; mt++)
        a_off[mt] = ((mb + mt * 16 + (lane & 15)) * PITCH + ((lane >> 4) & 1) * 4) * 4;
#pragma unroll
    for (int p = 0; p < 4; p++)
        b_off[p] = (A_WORDS + (nbo + p * 16 + ((lane >> 4) & 1) * 8 + (lane & 7)) * PITCH
                    + ((lane >> 3) & 1) * 4) * 4;

    auto load_stage = [&](int kk, int s) {
        float* base = sm + s * STAGE_WORDS;
        for (int idx = t; idx < 128 * 8; idx += NTH) {
            int row = idx >> 3, ch = (idx & 7) * 4;
            const float* src;
            if (MODE == 0) {
                int r = m0 + row; if (r >= NEMB) r = NEMB - 1;
                src = all_embs + (size_t)r * 256 + kk + ch;
            } else {
                src = g_ctx + (size_t)(m0 + row) * 256 + kk + ch;
            }
            cp_async16(base + row * PITCH + ch, src);
        }
        for (int idx = t; idx < BROWS * 8; idx += NTH) {
            int row = idx >> 3, ch = (idx & 7) * 4;
            cp_async16(base + A_WORDS + row * PITCH + ch,
                       Bmat + (size_t)row * 256 + kk + ch);
        }
    };

    float acc[2][8][4] = {};

    load_stage(0, 0);
    asm volatile("cp.async.commit_group;\n" ::: "memory");

#pragma unroll 1
    for (int it = 0; it < 8; ++it) {
        const int s = it & 1;
        asm volatile("cp.async.wait_group 0;\n" ::: "memory");
        __syncthreads();
        if (it + 1 < 8) load_stage((it + 1) * 32, s ^ 1);
        asm volatile("cp.async.commit_group;\n" ::: "memory");

        const uint32_t stage = sm_u32 + s * (STAGE_WORDS * 4);
#pragma unroll
        for (int ks = 0; ks < 4; ks++) {
            const uint32_t kbyte = ks * 32;
            uint32_t a[2][4];
#pragma unroll
            for (int mt = 0; mt < 2; mt++)
                ldsm_x4(a[mt][0], a[mt][1], a[mt][2], a[mt][3], stage + a_off[mt] + kbyte);
            uint32_t bf[8][2];
#pragma unroll
            for (int p = 0; p < 4; p++)
                ldsm_x4(bf[2 * p][0], bf[2 * p][1], bf[2 * p + 1][0], bf[2 * p + 1][1],
                        stage + b_off[p] + kbyte);
#pragma unroll
            for (int mt = 0; mt < 2; mt++)
#pragma unroll
                for (int nt = 0; nt < 8; nt++)
                    asm volatile(
                        "mma.sync.aligned.m16n8k8.row.col.f32.tf32.tf32.f32 "
                        "{%0,%1,%2,%3}, {%4,%5,%6,%7}, {%8,%9}, {%0,%1,%2,%3};\n"
                        : "+f"(acc[mt][nt][0]), "+f"(acc[mt][nt][1]),
                          "+f"(acc[mt][nt][2]), "+f"(acc[mt][nt][3])
                        : "r"(a[mt][0]), "r"(a[mt][1]), "r"(a[mt][2]), "r"(a[mt][3]),
                          "r"(bf[nt][0]), "r"(bf[nt][1]));
        }
        __syncthreads();
    }

    if (MODE == 0) {
#pragma unroll
        for (int mt = 0; mt < 2; mt++)
#pragma unroll
            for (int nt = 0; nt < 8; nt++) {
                int j = n0 + nbo + nt * 8 + tg * 2;   // [0,640)
#pragma unroll
                for (int h = 0; h < 2; h++) {
                    int row = m0 + mb + mt * 16 + g + h * 8;
                    if (row >= NEMB) continue;
                    float v0 = acc[mt][nt][h * 2 + 0];
                    float v1 = acc[mt][nt][h * 2 + 1];
                    if (j >= 384) {
                        v0 += bo[j - 384];
                        v1 += bo[j - 383];
                    } else if (j >= 128) {
                        v0 = 1.f / (1.f + __expf(-(v0 + bg[j - 128])));
                        v1 = 1.f / (1.f + __expf(-(v1 + bg[j - 127])));
                    }
                    *(float2*)(g_T + (size_t)row * 640 + j) = make_float2(v0, v1);
                }
            }
    } else {
        // MODE 1: + E1(table) + center, fused LayerNorm
        float rs[4] = {0.f, 0.f, 0.f, 0.f};
        float rq[4] = {0.f, 0.f, 0.f, 0.f};
#pragma unroll
        for (int mt = 0; mt < 2; mt++)
#pragma unroll
            for (int h = 0; h < 2; h++) {
                int lr = mb + mt * 16 + g + h * 8;
                const float* cen = all_embs + (size_t)ridx[lr] * 256;
                const float* e1r = g_T + (size_t)ridx[lr] * 640 + 384;
                float s = 0.f, q = 0.f;
#pragma unroll
                for (int nt = 0; nt < 8; nt++) {
                    int j = nbo + nt * 8 + tg * 2;
                    float2 e1 = *(const float2*)(e1r + j);
                    float2 c2 = *(const float2*)(cen + j);
                    float v0 = acc[mt][nt][h * 2 + 0] + e1.x + c2.x;
                    float v1 = acc[mt][nt][h * 2 + 1] + e1.y + c2.y;
                    acc[mt][nt][h * 2 + 0] = v0;
                    acc[mt][nt][h * 2 + 1] = v1;
                    s += v0 + v1;
                    q += v0 * v0 + v1 * v1;
                }
                rs[mt * 2 + h] = s;
                rq[mt * 2 + h] = q;
            }
#pragma unroll
        for (int i = 0; i < 4; i++) {
            rs[i] += __shfl_xor_sync(0xffffffffu, rs[i], 1);
            rs[i] += __shfl_xor_sync(0xffffffffu, rs[i], 2);
            rq[i] += __shfl_xor_sync(0xffffffffu, rq[i], 1);
            rq[i] += __shfl_xor_sync(0xffffffffu, rq[i], 2);
        }
        const int nw = warp >> 2;
        if (tg == 0) {
#pragma unroll
            for (int mt = 0; mt < 2; mt++)
#pragma unroll
                for (int h = 0; h < 2; h++) {
                    int lr = mb + mt * 16 + g + h * 8;
                    redS[lr][nw] = rs[mt * 2 + h];
                    redQ[lr][nw] = rq[mt * 2 + h];
                }
        }
        __syncthreads();
        float mu[4], rstd[4];
#pragma unroll
        for (int mt = 0; mt < 2; mt++)
#pragma unroll
            for (int h = 0; h < 2; h++) {
                int lr = mb + mt * 16 + g + h * 8;
                float s = redS[lr][0] + redS[lr][1] + redS[lr][2] + redS[lr][3];
                float q = redQ[lr][0] + redQ[lr][1] + redQ[lr][2] + redQ[lr][3];
                float m = s * (1.f / 256.f);
                float v = q * (1.f / 256.f) - m * m;
                mu[mt * 2 + h] = m;
                rstd[mt * 2 + h] = rsqrtf(v + 1e-5f);
            }
#pragma unroll
        for (int mt = 0; mt < 2; mt++)
#pragma unroll
            for (int nt = 0; nt < 8; nt++) {
                int j = nbo + nt * 8 + tg * 2;
                float2 gm = *(const float2*)(gamma + j);
                float2 bt = *(const float2*)(beta + j);
#pragma unroll
                for (int h = 0; h < 2; h++) {
                    int row = m0 + mb + mt * 16 + g + h * 8;
                    float m = mu[mt * 2 + h], r = rstd[mt * 2 + h];
                    float o0 = (acc[mt][nt][h * 2 + 0] - m) * r * gm.x + bt.x;
                    float o1 = (acc[mt][nt][h * 2 + 1] - m) * r * gm.y + bt.y;
                    *(float2*)(out + (size_t)row * 256 + j) = make_float2(o0, o1);
                }
            }
    }
}

// ---------------- neigh: streaming, one warp per row -----------------------
// q/ke/gate all gathered from the hot table g_T; neighbor rows streamed once.
__global__ __launch_bounds__(256)
void neigh_kernel(const float* __restrict__ all_embs,
                  const int* __restrict__ center_idx,
                  const int* __restrict__ nb_idx,
                  const float* __restrict__ nb_w) {
    const int warp = threadIdx.x >> 5;
    const int lane = threadIdx.x & 31;
    const int b = blockIdx.x * 8 + warp;

    const int cidx = center_idx[b];
    const float* trow = g_T + (size_t)cidx * 640;
    const float q0 = trow[lane];
    const float q1 = trow[32 + lane];

    int   myidx = 0;
    float myw   = 0.f;
    if (lane < 16) {
        myidx = nb_idx[b * 16 + lane];
        myw   = fmaxf(nb_w[b * 16 + lane], 1e-6f);
    }

    // logits: lane j keeps logit for neighbor j (j<16)
    float lgj = 0.f;
#pragma unroll
    for (int k = 0; k < 16; k++) {
        int r = __shfl_sync(0xffffffffu, myidx, k);
        const float* kp = g_T + (size_t)r * 640 + 64;
        float s = warp_sum(kp[lane] * q0 + kp[32 + lane] * q1);
        if (lane == k) lgj = s;
    }

    // softmax over 16 lanes (weights folded: w * exp(l - max))
    float l = (lane < 16) ? lgj * 0.125f : -1e30f;
    float mx = l;
#pragma unroll
    for (int off = 8; off >= 1; off >>= 1)
        mx = fmaxf(mx, __shfl_xor_sync(0xffffffffu, mx, off));
    float e = (lane < 16) ? myw * __expf(l - mx) : 0.f;
    float es = e;
#pragma unroll
    for (int off = 8; off >= 1; off >>= 1)
        es += __shfl_xor_sync(0xffffffffu, es, off);
    float ai = e / es;

    // context: stream neighbor rows once
    float4 a0 = make_float4(0, 0, 0, 0), a1 = make_float4(0, 0, 0, 0);
#pragma unroll
    for (int k = 0; k < 16; k++) {
        int   r  = __shfl_sync(0xffffffffu, myidx, k);
        float ak = __shfl_sync(0xffffffffu, ai, k);
        const float4* rp = (const float4*)(all_embs + (size_t)r * 256);
        float4 f0 = rp[lane], f1 = rp[32 + lane];
        a0.x = fmaf(ak, f0.x, a0.x); a0.y = fmaf(ak, f0.y, a0.y);
        a0.z = fmaf(ak, f0.z, a0.z); a0.w = fmaf(ak, f0.w, a0.w);
        a1.x = fmaf(ak, f1.x, a1.x); a1.y = fmaf(ak, f1.y, a1.y);
        a1.z = fmaf(ak, f1.z, a1.z); a1.w = fmaf(ak, f1.w, a1.w);
    }

    const float4* gp = (const float4*)(trow + 128);
    float4 g0 = gp[lane], g1 = gp[32 + lane];
    float4* crow = (float4*)(g_ctx + (size_t)b * 256);
    crow[lane]      = make_float4(g0.x * a0.x, g0.y * a0.y, g0.z * a0.z, g0.w * a0.w);
    crow[32 + lane] = make_float4(g1.x * a1.x, g1.y * a1.y, g1.z * a1.z, g1.w * a1.w);
}

// ---------------- launch ---------------------------------------------------
extern "C" void kernel_launch(void* const* d_in, const int* in_sizes, int n_in,
                              void* d_out, int out_size) {
    const float* all_embs   = (const float*)d_in[0];
    const int*   center_idx = (const int*)d_in[1];
    const int*   nb_idx     = (const int*)d_in[2];
    const float* nb_w       = (const float*)d_in[3];
    const float* Wq         = (const float*)d_in[4];
    const float* Wk         = (const float*)d_in[5];
    const float* Wg         = (const float*)d_in[6];
    const float* bg         = (const float*)d_in[7];
    const float* Wo         = (const float*)d_in[8];
    const float* bo         = (const float*)d_in[9];
    const float* gamma      = (const float*)d_in[10];
    const float* beta       = (const float*)d_in[11];
    float* out = (float*)d_out;

    const int sm128 = 2 * (128 + 128) * PITCH * 4;   // 73728
    const int sm256 = 2 * (128 + 256) * PITCH * 4;   // 110592

    static int configured = 0;
    if (!configured) {
        cudaFuncSetAttribute((const void*)gemm_kernel<0, 128, 256>,
                             cudaFuncAttributeMaxDynamicSharedMemorySize, sm128);
        cudaFuncSetAttribute((const void*)gemm_kernel<1, 256, 512>,
                             cudaFuncAttributeMaxDynamicSharedMemorySize, sm256);
        configured = 1;
    }

    prep_kernel<<<896, 256>>>(Wq, Wk, Wg, Wo);
    gemm_kernel<0, 128, 256><<<dim3((NEMB + 127) / 128, 5), 256, sm128>>>(
        all_embs, center_idx, bg, bo, gamma, beta, nullptr);                 // table q|ke|gate|E1
    neigh_kernel<<<BATCH / 8, 256>>>(all_embs, center_idx, nb_idx, nb_w);
    gemm_kernel<1, 256, 512><<<dim3(BATCH / 128, 1), 512, sm256>>>(
        all_embs, center_idx, bg, bo, gamma, beta, out);                     // out + LN
}

// round 9
// speedup vs baseline: 1.7346x; 1.0370x over previous
#include <cuda_runtime.h>
#include <cstdint>

#define BATCH 32768
#define NEMB  20000
#define PITCH 36
#define A_WORDS (128 * PITCH)

// ---------------- device scratch (static, allocation-free) ----------------
__device__ __align__(128) float g_WT[640 * 256];            // Wq|Wk|Wg|Wo1 rows, tf32-rounded
__device__ __align__(128) float g_W2[256 * 256];            // Wo2, tf32-rounded
__device__ __align__(128) float g_T[(size_t)NEMB * 640];    // per-table-row: q(64)|ke(64)|gate(256)|E1(256)
__device__ __align__(128) float g_ctx[(size_t)BATCH * 256]; // gated context

__device__ __forceinline__ float rnd_tf32(float x) {
    uint32_t y;
    asm("cvt.rna.tf32.f32 %0, %1;" : "=r"(y) : "f"(x));
    return __uint_as_float(y);
}
__device__ __forceinline__ void cp_async16(void* smem_dst, const void* gmem_src) {
    uint32_t s = (uint32_t)__cvta_generic_to_shared(smem_dst);
    asm volatile("cp.async.cg.shared.global [%0], [%1], 16;\n" :: "r"(s), "l"(gmem_src));
}
__device__ __forceinline__ void ldsm_x4(uint32_t& r0, uint32_t& r1, uint32_t& r2, uint32_t& r3,
                                        uint32_t saddr) {
    asm volatile("ldmatrix.sync.aligned.m8n8.x4.shared.b16 {%0,%1,%2,%3}, [%4];"
                 : "=r"(r0), "=r"(r1), "=r"(r2), "=r"(r3) : "r"(saddr));
}
__device__ __forceinline__ float warp_sum(float v) {
    v += __shfl_xor_sync(0xffffffffu, v, 16);
    v += __shfl_xor_sync(0xffffffffu, v, 8);
    v += __shfl_xor_sync(0xffffffffu, v, 4);
    v += __shfl_xor_sync(0xffffffffu, v, 2);
    v += __shfl_xor_sync(0xffffffffu, v, 1);
    return v;
}

// ---------------- K0: tf32-rounded weight assembly -------------------------
__global__ void prep_kernel(const float* __restrict__ Wq, const float* __restrict__ Wk,
                            const float* __restrict__ Wg, const float* __restrict__ Wo) {
    int j = blockIdx.x;
    int e = threadIdx.x;
    if (j < 64)        g_WT[j * 256 + e] = rnd_tf32(Wq[j * 256 + e]);
    else if (j < 128)  g_WT[j * 256 + e] = rnd_tf32(Wk[(j - 64) * 256 + e]);
    else if (j < 384)  g_WT[j * 256 + e] = rnd_tf32(Wg[(j - 128) * 256 + e]);
    else if (j < 640)  g_WT[j * 256 + e] = rnd_tf32(Wo[(j - 384) * 512 + e]);
    else               g_W2[(j - 640) * 256 + e] = rnd_tf32(Wo[(j - 640) * 512 + 256 + e]);
}

// ---------------- GEMM template (tf32 mma.sync, 2-stage cp.async) ----------
// Mainloop: ONE barrier per k-tile + fragment double-buffering across ks.
// MODE 0: table transform (A = all_embs contiguous, B = g_WT slab) -> g_T
// MODE 1: A = g_ctx, B = g_W2 -> + E1(table) + center, fused LayerNorm -> out
template <int MODE, int BROWS, int NTH>
__global__ __launch_bounds__(NTH, (NTH == 512) ? 1 : 2)
void gemm_kernel(const float* __restrict__ all_embs,
                 const int* __restrict__ center_idx,
                 const float* __restrict__ bg,
                 const float* __restrict__ bo,
                 const float* __restrict__ gamma,
                 const float* __restrict__ beta,
                 float* __restrict__ out) {
    constexpr int STAGE_WORDS = (128 + BROWS) * PITCH;
    extern __shared__ float sm[];
    __shared__ int   ridx[128];
    __shared__ float redS[128][4];
    __shared__ float redQ[128][4];

    const int t    = threadIdx.x;
    const int lane = t & 31;
    const int warp = t >> 5;
    const int m0 = blockIdx.x * 128;
    const int n0 = blockIdx.y * BROWS;
    const float* Bmat = (MODE == 0) ? (g_WT + (size_t)n0 * 256) : g_W2;

    if (MODE == 1 && t < 128) ridx[t] = center_idx[m0 + t];
    __syncthreads();

    const uint32_t sm_u32 = (uint32_t)__cvta_generic_to_shared(sm);
    const int g   = lane >> 2;
    const int tg  = lane & 3;
    const int mb  = (warp & 3) * 32;
    const int nbo = (warp >> 2) * 64;

    uint32_t a_off[2], b_off[4];
#pragma unroll
    for (int mt = 0; mt < 2; mt++)
        a_off[mt] = ((mb + mt * 16 + (lane & 15)) * PITCH + ((lane >> 4) & 1) * 4) * 4;
#pragma unroll
    for (int p = 0; p < 4; p++)
        b_off[p] = (A_WORDS + (nbo + p * 16 + ((lane >> 4) & 1) * 8 + (lane & 7)) * PITCH
                    + ((lane >> 3) & 1) * 4) * 4;

    auto load_stage = [&](int kk, int s) {
        float* base = sm + s * STAGE_WORDS;
        for (int idx = t; idx < 128 * 8; idx += NTH) {
            int row = idx >> 3, ch = (idx & 7) * 4;
            const float* src;
            if (MODE == 0) {
                int r = m0 + row; if (r >= NEMB) r = NEMB - 1;
                src = all_embs + (size_t)r * 256 + kk + ch;
            } else {
                src = g_ctx + (size_t)(m0 + row) * 256 + kk + ch;
            }
            cp_async16(base + row * PITCH + ch, src);
        }
        for (int idx = t; idx < BROWS * 8; idx += NTH) {
            int row = idx >> 3, ch = (idx & 7) * 4;
            cp_async16(base + A_WORDS + row * PITCH + ch,
                       Bmat + (size_t)row * 256 + kk + ch);
        }
    };

    float acc[2][8][4] = {};
    uint32_t af[2][2][4];     // [buf][mt][4]
    uint32_t bf[2][8][2];     // [buf][nt][2]

    auto load_frags = [&](uint32_t stage, int ks, int buf) {
        const uint32_t kbyte = ks * 32;
#pragma unroll
        for (int mt = 0; mt < 2; mt++)
            ldsm_x4(af[buf][mt][0], af[buf][mt][1], af[buf][mt][2], af[buf][mt][3],
                    stage + a_off[mt] + kbyte);
#pragma unroll
        for (int p = 0; p < 4; p++)
            ldsm_x4(bf[buf][2 * p][0], bf[buf][2 * p][1], bf[buf][2 * p + 1][0],
                    bf[buf][2 * p + 1][1], stage + b_off[p] + kbyte);
    };

    load_stage(0, 0);
    asm volatile("cp.async.commit_group;\n" ::: "memory");

#pragma unroll 1
    for (int it = 0; it < 8; ++it) {
        const int s = it & 1;
        asm volatile("cp.async.wait_group 0;\n" ::: "memory");
        __syncthreads();                    // single barrier per k-tile
        if (it + 1 < 8) load_stage((it + 1) * 32, s ^ 1);
        asm volatile("cp.async.commit_group;\n" ::: "memory");

        const uint32_t stage = sm_u32 + s * (STAGE_WORDS * 4);
        load_frags(stage, 0, 0);
#pragma unroll
        for (int ks = 0; ks < 4; ks++) {
            const int cur = ks & 1;
            if (ks < 3) load_frags(stage, ks + 1, cur ^ 1);
#pragma unroll
            for (int mt = 0; mt < 2; mt++)
#pragma unroll
                for (int nt = 0; nt < 8; nt++)
                    asm volatile(
                        "mma.sync.aligned.m16n8k8.row.col.f32.tf32.tf32.f32 "
                        "{%0,%1,%2,%3}, {%4,%5,%6,%7}, {%8,%9}, {%0,%1,%2,%3};\n"
                        : "+f"(acc[mt][nt][0]), "+f"(acc[mt][nt][1]),
                          "+f"(acc[mt][nt][2]), "+f"(acc[mt][nt][3])
                        : "r"(af[cur][mt][0]), "r"(af[cur][mt][1]),
                          "r"(af[cur][mt][2]), "r"(af[cur][mt][3]),
                          "r"(bf[cur][nt][0]), "r"(bf[cur][nt][1]));
        }
    }

    if (MODE == 0) {
#pragma unroll
        for (int mt = 0; mt < 2; mt++)
#pragma unroll
            for (int nt = 0; nt < 8; nt++) {
                int j = n0 + nbo + nt * 8 + tg * 2;   // [0,640)
#pragma unroll
                for (int h = 0; h < 2; h++) {
                    int row = m0 + mb + mt * 16 + g + h * 8;
                    if (row >= NEMB) continue;
                    float v0 = acc[mt][nt][h * 2 + 0];
                    float v1 = acc[mt][nt][h * 2 + 1];
                    if (j >= 384) {
                        v0 += bo[j - 384];
                        v1 += bo[j - 383];
                    } else if (j >= 128) {
                        v0 = 1.f / (1.f + __expf(-(v0 + bg[j - 128])));
                        v1 = 1.f / (1.f + __expf(-(v1 + bg[j - 127])));
                    }
                    *(float2*)(g_T + (size_t)row * 640 + j) = make_float2(v0, v1);
                }
            }
    } else {
        // MODE 1: + E1(table) + center, fused LayerNorm
        float rs[4] = {0.f, 0.f, 0.f, 0.f};
        float rq[4] = {0.f, 0.f, 0.f, 0.f};
#pragma unroll
        for (int mt = 0; mt < 2; mt++)
#pragma unroll
            for (int h = 0; h < 2; h++) {
                int lr = mb + mt * 16 + g + h * 8;
                const float* cen = all_embs + (size_t)ridx[lr] * 256;
                const float* e1r = g_T + (size_t)ridx[lr] * 640 + 384;
                float s = 0.f, q = 0.f;
#pragma unroll
                for (int nt = 0; nt < 8; nt++) {
                    int j = nbo + nt * 8 + tg * 2;
                    float2 e1 = *(const float2*)(e1r + j);
                    float2 c2 = *(const float2*)(cen + j);
                    float v0 = acc[mt][nt][h * 2 + 0] + e1.x + c2.x;
                    float v1 = acc[mt][nt][h * 2 + 1] + e1.y + c2.y;
                    acc[mt][nt][h * 2 + 0] = v0;
                    acc[mt][nt][h * 2 + 1] = v1;
                    s += v0 + v1;
                    q += v0 * v0 + v1 * v1;
                }
                rs[mt * 2 + h] = s;
                rq[mt * 2 + h] = q;
            }
#pragma unroll
        for (int i = 0; i < 4; i++) {
            rs[i] += __shfl_xor_sync(0xffffffffu, rs[i], 1);
            rs[i] += __shfl_xor_sync(0xffffffffu, rs[i], 2);
            rq[i] += __shfl_xor_sync(0xffffffffu, rq[i], 1);
            rq[i] += __shfl_xor_sync(0xffffffffu, rq[i], 2);
        }
        const int nw = warp >> 2;
        if (tg == 0) {
#pragma unroll
            for (int mt = 0; mt < 2; mt++)
#pragma unroll
                for (int h = 0; h < 2; h++) {
                    int lr = mb + mt * 16 + g + h * 8;
                    redS[lr][nw] = rs[mt * 2 + h];
                    redQ[lr][nw] = rq[mt * 2 + h];
                }
        }
        __syncthreads();
        float mu[4], rstd[4];
#pragma unroll
        for (int mt = 0; mt < 2; mt++)
#pragma unroll
            for (int h = 0; h < 2; h++) {
                int lr = mb + mt * 16 + g + h * 8;
                float s = redS[lr][0] + redS[lr][1] + redS[lr][2] + redS[lr][3];
                float q = redQ[lr][0] + redQ[lr][1] + redQ[lr][2] + redQ[lr][3];
                float m = s * (1.f / 256.f);
                float v = q * (1.f / 256.f) - m * m;
                mu[mt * 2 + h] = m;
                rstd[mt * 2 + h] = rsqrtf(v + 1e-5f);
            }
#pragma unroll
        for (int mt = 0; mt < 2; mt++)
#pragma unroll
            for (int nt = 0; nt < 8; nt++) {
                int j = nbo + nt * 8 + tg * 2;
                float2 gm = *(const float2*)(gamma + j);
                float2 bt = *(const float2*)(beta + j);
#pragma unroll
                for (int h = 0; h < 2; h++) {
                    int row = m0 + mb + mt * 16 + g + h * 8;
                    float m = mu[mt * 2 + h], r = rstd[mt * 2 + h];
                    float o0 = (acc[mt][nt][h * 2 + 0] - m) * r * gm.x + bt.x;
                    float o1 = (acc[mt][nt][h * 2 + 1] - m) * r * gm.y + bt.y;
                    *(float2*)(out + (size_t)row * 256 + j) = make_float2(o0, o1);
                }
            }
    }
}

// ---------------- neigh: streaming, one warp per row -----------------------
__global__ __launch_bounds__(256)
void neigh_kernel(const float* __restrict__ all_embs,
                  const int* __restrict__ center_idx,
                  const int* __restrict__ nb_idx,
                  const float* __restrict__ nb_w) {
    const int warp = threadIdx.x >> 5;
    const int lane = threadIdx.x & 31;
    const int b = blockIdx.x * 8 + warp;

    const int cidx = center_idx[b];
    const float* trow = g_T + (size_t)cidx * 640;
    const float q0 = trow[lane];
    const float q1 = trow[32 + lane];

    int   myidx = 0;
    float myw   = 0.f;
    if (lane < 16) {
        myidx = nb_idx[b * 16 + lane];
        myw   = fmaxf(nb_w[b * 16 + lane], 1e-6f);
    }

    // logits: lane j keeps logit for neighbor j (j<16)
    float lgj = 0.f;
#pragma unroll
    for (int k = 0; k < 16; k++) {
        int r = __shfl_sync(0xffffffffu, myidx, k);
        const float* kp = g_T + (size_t)r * 640 + 64;
        float s = warp_sum(kp[lane] * q0 + kp[32 + lane] * q1);
        if (lane == k) lgj = s;
    }

    // softmax over 16 lanes (weights folded: w * exp(l - max))
    float l = (lane < 16) ? lgj * 0.125f : -1e30f;
    float mx = l;
#pragma unroll
    for (int off = 8; off >= 1; off >>= 1)
        mx = fmaxf(mx, __shfl_xor_sync(0xffffffffu, mx, off));
    float e = (lane < 16) ? myw * __expf(l - mx) : 0.f;
    float es = e;
#pragma unroll
    for (int off = 8; off >= 1; off >>= 1)
        es += __shfl_xor_sync(0xffffffffu, es, off);
    float ai = e / es;

    // context: stream neighbor rows once
    float4 a0 = make_float4(0, 0, 0, 0), a1 = make_float4(0, 0, 0, 0);
#pragma unroll
    for (int k = 0; k < 16; k++) {
        int   r  = __shfl_sync(0xffffffffu, myidx, k);
        float ak = __shfl_sync(0xffffffffu, ai, k);
        const float4* rp = (const float4*)(all_embs + (size_t)r * 256);
        float4 f0 = rp[lane], f1 = rp[32 + lane];
        a0.x = fmaf(ak, f0.x, a0.x); a0.y = fmaf(ak, f0.y, a0.y);
        a0.z = fmaf(ak, f0.z, a0.z); a0.w = fmaf(ak, f0.w, a0.w);
        a1.x = fmaf(ak, f1.x, a1.x); a1.y = fmaf(ak, f1.y, a1.y);
        a1.z = fmaf(ak, f1.z, a1.z); a1.w = fmaf(ak, f1.w, a1.w);
    }

    const float4* gp = (const float4*)(trow + 128);
    float4 g0 = gp[lane], g1 = gp[32 + lane];
    float4* crow = (float4*)(g_ctx + (size_t)b * 256);
    crow[lane]      = make_float4(g0.x * a0.x, g0.y * a0.y, g0.z * a0.z, g0.w * a0.w);
    crow[32 + lane] = make_float4(g1.x * a1.x, g1.y * a1.y, g1.z * a1.z, g1.w * a1.w);
}

// ---------------- launch ---------------------------------------------------
extern "C" void kernel_launch(void* const* d_in, const int* in_sizes, int n_in,
                              void* d_out, int out_size) {
    const float* all_embs   = (const float*)d_in[0];
    const int*   center_idx = (const int*)d_in[1];
    const int*   nb_idx     = (const int*)d_in[2];
    const float* nb_w       = (const float*)d_in[3];
    const float* Wq         = (const float*)d_in[4];
    const float* Wk         = (const float*)d_in[5];
    const float* Wg         = (const float*)d_in[6];
    const float* bg         = (const float*)d_in[7];
    const float* Wo         = (const float*)d_in[8];
    const float* bo         = (const float*)d_in[9];
    const float* gamma      = (const float*)d_in[10];
    const float* beta       = (const float*)d_in[11];
    float* out = (float*)d_out;

    const int sm128 = 2 * (128 + 128) * PITCH * 4;   // 73728
    const int sm256 = 2 * (128 + 256) * PITCH * 4;   // 110592

    static int configured = 0;
    if (!configured) {
        cudaFuncSetAttribute((const void*)gemm_kernel<0, 128, 256>,
                             cudaFuncAttributeMaxDynamicSharedMemorySize, sm128);
        cudaFuncSetAttribute((const void*)gemm_kernel<1, 256, 512>,
                             cudaFuncAttributeMaxDynamicSharedMemorySize, sm256);
        configured = 1;
    }

    prep_kernel<<<896, 256>>>(Wq, Wk, Wg, Wo);
    gemm_kernel<0, 128, 256><<<dim3((NEMB + 127) / 128, 5), 256, sm128>>>(
        all_embs, center_idx, bg, bo, gamma, beta, nullptr);                 // table q|ke|gate|E1
    neigh_kernel<<<BATCH / 8, 256>>>(all_embs, center_idx, nb_idx, nb_w);
    gemm_kernel<1, 256, 512><<<dim3(BATCH / 128, 1), 512, sm256>>>(
        all_embs, center_idx, bg, bo, gamma, beta, out);                     // out + LN
}

// round 10
// speedup vs baseline: 2.0903x; 1.2050x over previous
#include <cuda_runtime.h>
#include <cuda_fp16.h>
#include <cstdint>

#define BATCH 32768
#define NEMB  20000
#define RPITCH 144                 // bytes per smem row (64 halfs used + pad)
#define A_BYTES (128 * RPITCH)

// ---------------- device scratch (static, allocation-free) ----------------
__device__ __align__(128) __half g_WTh[640 * 256];          // Wq|Wk|Wg|Wo1 rows (fp16)
__device__ __align__(128) __half g_W2h[256 * 256];          // Wo2 (fp16)
__device__ __align__(128) __half g_embh[(size_t)NEMB * 256];// fp16 embedding copy
__device__ __align__(128) __half g_ctxh[(size_t)BATCH * 256];// gated context (fp16)
__device__ __align__(128) float  g_T[(size_t)NEMB * 640];   // q(64)|ke(64)|gate(256)|E1(256)

__device__ __forceinline__ void cp_async16(uint32_t smem_dst, const void* gmem_src) {
    asm volatile("cp.async.cg.shared.global [%0], [%1], 16;\n" :: "r"(smem_dst), "l"(gmem_src));
}
__device__ __forceinline__ void ldsm_x4(uint32_t& r0, uint32_t& r1, uint32_t& r2, uint32_t& r3,
                                        uint32_t saddr) {
    asm volatile("ldmatrix.sync.aligned.m8n8.x4.shared.b16 {%0,%1,%2,%3}, [%4];"
                 : "=r"(r0), "=r"(r1), "=r"(r2), "=r"(r3) : "r"(saddr));
}
__device__ __forceinline__ float warp_sum(float v) {
    v += __shfl_xor_sync(0xffffffffu, v, 16);
    v += __shfl_xor_sync(0xffffffffu, v, 8);
    v += __shfl_xor_sync(0xffffffffu, v, 4);
    v += __shfl_xor_sync(0xffffffffu, v, 2);
    v += __shfl_xor_sync(0xffffffffu, v, 1);
    return v;
}

// ---------------- K0: fp16 weight assembly ---------------------------------
__global__ void prep_kernel(const float* __restrict__ Wq, const float* __restrict__ Wk,
                            const float* __restrict__ Wg, const float* __restrict__ Wo) {
    int j = blockIdx.x;
    int e = threadIdx.x;
    if (j < 64)        g_WTh[j * 256 + e] = __float2half_rn(Wq[j * 256 + e]);
    else if (j < 128)  g_WTh[j * 256 + e] = __float2half_rn(Wk[(j - 64) * 256 + e]);
    else if (j < 384)  g_WTh[j * 256 + e] = __float2half_rn(Wg[(j - 128) * 256 + e]);
    else if (j < 640)  g_WTh[j * 256 + e] = __float2half_rn(Wo[(j - 384) * 512 + e]);
    else               g_W2h[(j - 640) * 256 + e] = __float2half_rn(Wo[(j - 640) * 512 + 256 + e]);
}

// ---------------- K0b: fp16 embedding copy ---------------------------------
__global__ void emb_cvt_kernel(const float* __restrict__ e) {
    size_t i = ((size_t)blockIdx.x * 256 + threadIdx.x) * 8;   // 8 elems/thread
    float4 f0 = *(const float4*)(e + i);
    float4 f1 = *(const float4*)(e + i + 4);
    __half2 h[4];
    h[0] = __floats2half2_rn(f0.x, f0.y);
    h[1] = __floats2half2_rn(f0.z, f0.w);
    h[2] = __floats2half2_rn(f1.x, f1.y);
    h[3] = __floats2half2_rn(f1.z, f1.w);
    *(uint4*)(g_embh + i) = *(uint4*)h;
}

// ---------------- GEMM template (fp16 m16n8k16, 2-stage cp.async) ----------
// K-tile = 64 halfs (128B rows), 4 tiles; frag double-buffer; 1 barrier/tile.
// MODE 0: A = g_embh (contiguous), B = g_WTh slab -> g_T (epilogue by region)
// MODE 1: A = g_ctxh, B = g_W2h -> + E1(table) + center, fused LN -> out
template <int MODE, int BROWS, int NTH>
__global__ __launch_bounds__(NTH, (NTH == 512) ? 1 : 2)
void gemm_kernel(const float* __restrict__ all_embs,
                 const int* __restrict__ center_idx,
                 const float* __restrict__ bg,
                 const float* __restrict__ bo,
                 const float* __restrict__ gamma,
                 const float* __restrict__ beta,
                 float* __restrict__ out) {
    constexpr int STAGE_BYTES = (128 + BROWS) * RPITCH;
    extern __shared__ char sm[];
    __shared__ int   ridx[128];
    __shared__ float redS[128][4];
    __shared__ float redQ[128][4];

    const int t    = threadIdx.x;
    const int lane = t & 31;
    const int warp = t >> 5;
    const int m0 = blockIdx.x * 128;
    const int n0 = blockIdx.y * BROWS;
    const __half* Bmat = (MODE == 0) ? (g_WTh + (size_t)n0 * 256) : g_W2h;

    if (MODE == 1 && t < 128) ridx[t] = center_idx[m0 + t];
    __syncthreads();

    const uint32_t sm_u32 = (uint32_t)__cvta_generic_to_shared(sm);
    const int g   = lane >> 2;
    const int tg  = lane & 3;
    const int mb  = (warp & 3) * 32;
    const int nbo = (warp >> 2) * 64;

    uint32_t a_off[2], b_off[4];
#pragma unroll
    for (int mt = 0; mt < 2; mt++)
        a_off[mt] = (mb + mt * 16 + (lane & 15)) * RPITCH + ((lane >> 4) & 1) * 16;
#pragma unroll
    for (int p = 0; p < 4; p++)
        b_off[p] = A_BYTES + (nbo + p * 16 + ((lane >> 4) & 1) * 8 + (lane & 7)) * RPITCH
                   + ((lane >> 3) & 1) * 16;

    auto load_stage = [&](int kt, int s) {
        const uint32_t dst0 = sm_u32 + s * STAGE_BYTES;
        const int kk = kt * 64;                      // halfs
        for (int idx = t; idx < 128 * 8; idx += NTH) {
            int row = idx >> 3, ch = idx & 7;
            const __half* src;
            if (MODE == 0) {
                int r = m0 + row; if (r >= NEMB) r = NEMB - 1;
                src = g_embh + (size_t)r * 256 + kk + ch * 8;
            } else {
                src = g_ctxh + (size_t)(m0 + row) * 256 + kk + ch * 8;
            }
            cp_async16(dst0 + row * RPITCH + ch * 16, src);
        }
        for (int idx = t; idx < BROWS * 8; idx += NTH) {
            int row = idx >> 3, ch = idx & 7;
            cp_async16(dst0 + A_BYTES + row * RPITCH + ch * 16,
                       Bmat + (size_t)row * 256 + kk + ch * 8);
        }
    };

    float acc[2][8][4] = {};
    uint32_t af[2][2][4];
    uint32_t bf[2][8][2];

    auto load_frags = [&](uint32_t stage, int ks, int buf) {
        const uint32_t kbyte = ks * 32;              // 16 halfs
#pragma unroll
        for (int mt = 0; mt < 2; mt++)
            ldsm_x4(af[buf][mt][0], af[buf][mt][1], af[buf][mt][2], af[buf][mt][3],
                    stage + a_off[mt] + kbyte);
#pragma unroll
        for (int p = 0; p < 4; p++)
            ldsm_x4(bf[buf][2 * p][0], bf[buf][2 * p][1], bf[buf][2 * p + 1][0],
                    bf[buf][2 * p + 1][1], stage + b_off[p] + kbyte);
    };

    load_stage(0, 0);
    asm volatile("cp.async.commit_group;\n" ::: "memory");

#pragma unroll 1
    for (int it = 0; it < 4; ++it) {
        const int s = it & 1;
        asm volatile("cp.async.wait_group 0;\n" ::: "memory");
        __syncthreads();
        if (it + 1 < 4) load_stage(it + 1, s ^ 1);
        asm volatile("cp.async.commit_group;\n" ::: "memory");

        const uint32_t stage = sm_u32 + s * STAGE_BYTES;
        load_frags(stage, 0, 0);
#pragma unroll
        for (int ks = 0; ks < 4; ks++) {
            const int cur = ks & 1;
            if (ks < 3) load_frags(stage, ks + 1, cur ^ 1);
#pragma unroll
            for (int mt = 0; mt < 2; mt++)
#pragma unroll
                for (int nt = 0; nt < 8; nt++)
                    asm volatile(
                        "mma.sync.aligned.m16n8k16.row.col.f32.f16.f16.f32 "
                        "{%0,%1,%2,%3}, {%4,%5,%6,%7}, {%8,%9}, {%0,%1,%2,%3};\n"
                        : "+f"(acc[mt][nt][0]), "+f"(acc[mt][nt][1]),
                          "+f"(acc[mt][nt][2]), "+f"(acc[mt][nt][3])
                        : "r"(af[cur][mt][0]), "r"(af[cur][mt][1]),
                          "r"(af[cur][mt][2]), "r"(af[cur][mt][3]),
                          "r"(bf[cur][nt][0]), "r"(bf[cur][nt][1]));
        }
    }

    if (MODE == 0) {
#pragma unroll
        for (int mt = 0; mt < 2; mt++)
#pragma unroll
            for (int nt = 0; nt < 8; nt++) {
                int j = n0 + nbo + nt * 8 + tg * 2;   // [0,640)
#pragma unroll
                for (int h = 0; h < 2; h++) {
                    int row = m0 + mb + mt * 16 + g + h * 8;
                    if (row >= NEMB) continue;
                    float v0 = acc[mt][nt][h * 2 + 0];
                    float v1 = acc[mt][nt][h * 2 + 1];
                    if (j >= 384) {
                        v0 += bo[j - 384];
                        v1 += bo[j - 383];
                    } else if (j >= 128) {
                        v0 = 1.f / (1.f + __expf(-(v0 + bg[j - 128])));
                        v1 = 1.f / (1.f + __expf(-(v1 + bg[j - 127])));
                    }
                    *(float2*)(g_T + (size_t)row * 640 + j) = make_float2(v0, v1);
                }
            }
    } else {
        // MODE 1: + E1(table) + center, fused LayerNorm
        float rs[4] = {0.f, 0.f, 0.f, 0.f};
        float rq[4] = {0.f, 0.f, 0.f, 0.f};
#pragma unroll
        for (int mt = 0; mt < 2; mt++)
#pragma unroll
            for (int h = 0; h < 2; h++) {
                int lr = mb + mt * 16 + g + h * 8;
                const float* cen = all_embs + (size_t)ridx[lr] * 256;
                const float* e1r = g_T + (size_t)ridx[lr] * 640 + 384;
                float s = 0.f, q = 0.f;
#pragma unroll
                for (int nt = 0; nt < 8; nt++) {
                    int j = nbo + nt * 8 + tg * 2;
                    float2 e1 = *(const float2*)(e1r + j);
                    float2 c2 = *(const float2*)(cen + j);
                    float v0 = acc[mt][nt][h * 2 + 0] + e1.x + c2.x;
                    float v1 = acc[mt][nt][h * 2 + 1] + e1.y + c2.y;
                    acc[mt][nt][h * 2 + 0] = v0;
                    acc[mt][nt][h * 2 + 1] = v1;
                    s += v0 + v1;
                    q += v0 * v0 + v1 * v1;
                }
                rs[mt * 2 + h] = s;
                rq[mt * 2 + h] = q;
            }
#pragma unroll
        for (int i = 0; i < 4; i++) {
            rs[i] += __shfl_xor_sync(0xffffffffu, rs[i], 1);
            rs[i] += __shfl_xor_sync(0xffffffffu, rs[i], 2);
            rq[i] += __shfl_xor_sync(0xffffffffu, rq[i], 1);
            rq[i] += __shfl_xor_sync(0xffffffffu, rq[i], 2);
        }
        const int nw = warp >> 2;
        if (tg == 0) {
#pragma unroll
            for (int mt = 0; mt < 2; mt++)
#pragma unroll
                for (int h = 0; h < 2; h++) {
                    int lr = mb + mt * 16 + g + h * 8;
                    redS[lr][nw] = rs[mt * 2 + h];
                    redQ[lr][nw] = rq[mt * 2 + h];
                }
        }
        __syncthreads();
        float mu[4], rstd[4];
#pragma unroll
        for (int mt = 0; mt < 2; mt++)
#pragma unroll
            for (int h = 0; h < 2; h++) {
                int lr = mb + mt * 16 + g + h * 8;
                float s = redS[lr][0] + redS[lr][1] + redS[lr][2] + redS[lr][3];
                float q = redQ[lr][0] + redQ[lr][1] + redQ[lr][2] + redQ[lr][3];
                float m = s * (1.f / 256.f);
                float v = q * (1.f / 256.f) - m * m;
                mu[mt * 2 + h] = m;
                rstd[mt * 2 + h] = rsqrtf(v + 1e-5f);
            }
#pragma unroll
        for (int mt = 0; mt < 2; mt++)
#pragma unroll
            for (int nt = 0; nt < 8; nt++) {
                int j = nbo + nt * 8 + tg * 2;
                float2 gm = *(const float2*)(gamma + j);
                float2 bt = *(const float2*)(beta + j);
#pragma unroll
                for (int h = 0; h < 2; h++) {
                    int row = m0 + mb + mt * 16 + g + h * 8;
                    float m = mu[mt * 2 + h], r = rstd[mt * 2 + h];
                    float o0 = (acc[mt][nt][h * 2 + 0] - m) * r * gm.x + bt.x;
                    float o1 = (acc[mt][nt][h * 2 + 1] - m) * r * gm.y + bt.y;
                    *(float2*)(out + (size_t)row * 256 + j) = make_float2(o0, o1);
                }
            }
    }
}

// ---------------- neigh: streaming, one warp per row -----------------------
__global__ __launch_bounds__(256)
void neigh_kernel(const float* __restrict__ all_embs,
                  const int* __restrict__ center_idx,
                  const int* __restrict__ nb_idx,
                  const float* __restrict__ nb_w) {
    const int warp = threadIdx.x >> 5;
    const int lane = threadIdx.x & 31;
    const int b = blockIdx.x * 8 + warp;

    const int cidx = center_idx[b];
    const float* trow = g_T + (size_t)cidx * 640;
    const float q0 = trow[lane];
    const float q1 = trow[32 + lane];

    int   myidx = 0;
    float myw   = 0.f;
    if (lane < 16) {
        myidx = nb_idx[b * 16 + lane];
        myw   = fmaxf(nb_w[b * 16 + lane], 1e-6f);
    }

    // logits: lane j keeps logit for neighbor j (j<16)
    float lgj = 0.f;
#pragma unroll
    for (int k = 0; k < 16; k++) {
        int r = __shfl_sync(0xffffffffu, myidx, k);
        const float* kp = g_T + (size_t)r * 640 + 64;
        float s = warp_sum(kp[lane] * q0 + kp[32 + lane] * q1);
        if (lane == k) lgj = s;
    }

    // softmax over 16 lanes (weights folded: w * exp(l - max))
    float l = (lane < 16) ? lgj * 0.125f : -1e30f;
    float mx = l;
#pragma unroll
    for (int off = 8; off >= 1; off >>= 1)
        mx = fmaxf(mx, __shfl_xor_sync(0xffffffffu, mx, off));
    float e = (lane < 16) ? myw * __expf(l - mx) : 0.f;
    float es = e;
#pragma unroll
    for (int off = 8; off >= 1; off >>= 1)
        es += __shfl_xor_sync(0xffffffffu, es, off);
    float ai = e / es;

    // context: stream neighbor rows once
    float4 a0 = make_float4(0, 0, 0, 0), a1 = make_float4(0, 0, 0, 0);
#pragma unroll
    for (int k = 0; k < 16; k++) {
        int   r  = __shfl_sync(0xffffffffu, myidx, k);
        float ak = __shfl_sync(0xffffffffu, ai, k);
        const float4* rp = (const float4*)(all_embs + (size_t)r * 256);
        float4 f0 = rp[lane], f1 = rp[32 + lane];
        a0.x = fmaf(ak, f0.x, a0.x); a0.y = fmaf(ak, f0.y, a0.y);
        a0.z = fmaf(ak, f0.z, a0.z); a0.w = fmaf(ak, f0.w, a0.w);
        a1.x = fmaf(ak, f1.x, a1.x); a1.y = fmaf(ak, f1.y, a1.y);
        a1.z = fmaf(ak, f1.z, a1.z); a1.w = fmaf(ak, f1.w, a1.w);
    }

    const float4* gp = (const float4*)(trow + 128);
    float4 g0 = gp[lane], g1 = gp[32 + lane];

    __half2 h[4];
    __half* crow = g_ctxh + (size_t)b * 256;
    h[0] = __floats2half2_rn(g0.x * a0.x, g0.y * a0.y);
    h[1] = __floats2half2_rn(g0.z * a0.z, g0.w * a0.w);
    *(uint2*)(crow + lane * 4) = *(uint2*)h;
    h[2] = __floats2half2_rn(g1.x * a1.x, g1.y * a1.y);
    h[3] = __floats2half2_rn(g1.z * a1.z, g1.w * a1.w);
    *(uint2*)(crow + 128 + lane * 4) = *(uint2*)(h + 2);
}

// ---------------- launch ---------------------------------------------------
extern "C" void kernel_launch(void* const* d_in, const int* in_sizes, int n_in,
                              void* d_out, int out_size) {
    const float* all_embs   = (const float*)d_in[0];
    const int*   center_idx = (const int*)d_in[1];
    const int*   nb_idx     = (const int*)d_in[2];
    const float* nb_w       = (const float*)d_in[3];
    const float* Wq         = (const float*)d_in[4];
    const float* Wk         = (const float*)d_in[5];
    const float* Wg         = (const float*)d_in[6];
    const float* bg         = (const float*)d_in[7];
    const float* Wo         = (const float*)d_in[8];
    const float* bo         = (const float*)d_in[9];
    const float* gamma      = (const float*)d_in[10];
    const float* beta       = (const float*)d_in[11];
    float* out = (float*)d_out;

    const int sm128 = 2 * (128 + 128) * RPITCH;   // 73728
    const int sm256 = 2 * (128 + 256) * RPITCH;   // 110592

    static int configured = 0;
    if (!configured) {
        cudaFuncSetAttribute((const void*)gemm_kernel<0, 128, 256>,
                             cudaFuncAttributeMaxDynamicSharedMemorySize, sm128);
        cudaFuncSetAttribute((const void*)gemm_kernel<1, 256, 512>,
                             cudaFuncAttributeMaxDynamicSharedMemorySize, sm256);
        configured = 1;
    }

    prep_kernel<<<896, 256>>>(Wq, Wk, Wg, Wo);
    emb_cvt_kernel<<<2500, 256>>>(all_embs);
    gemm_kernel<0, 128, 256><<<dim3((NEMB + 127) / 128, 5), 256, sm128>>>(
        all_embs, center_idx, bg, bo, gamma, beta, nullptr);                 // table q|ke|gate|E1
    neigh_kernel<<<BATCH / 8, 256>>>(all_embs, center_idx, nb_idx, nb_w);
    gemm_kernel<1, 256, 512><<<dim3(BATCH / 128, 1), 512, sm256>>>(
        all_embs, center_idx, bg, bo, gamma, beta, out);                     // out + LN
}

// round 11
// speedup vs baseline: 2.2660x; 1.0840x over previous
#include <cuda_runtime.h>
#include <cuda_fp16.h>
#include <cstdint>

#define BATCH 32768
#define NEMB  20000
#define RPITCH 144                 // bytes per smem row (64 halfs used + pad)
#define A_BYTES (128 * RPITCH)

// ---------------- device scratch (static, allocation-free) ----------------
__device__ __align__(128) __half g_WTh[640 * 256];           // Wq|Wk|Wg|Wo1 rows (fp16)
__device__ __align__(128) __half g_W2h[256 * 256];           // Wo2 (fp16)
__device__ __align__(128) __half g_embh[(size_t)NEMB * 256]; // fp16 embedding copy
__device__ __align__(128) __half g_keh[(size_t)NEMB * 64];   // fp16 ke table
__device__ __align__(128) __half g_ctxh[(size_t)BATCH * 256];// gated context (fp16)
__device__ __align__(128) float  g_T[(size_t)NEMB * 640];    // q(64)|ke(64)|gate(256)|E1(256)

__device__ __forceinline__ void cp_async16(uint32_t smem_dst, const void* gmem_src) {
    asm volatile("cp.async.cg.shared.global [%0], [%1], 16;\n" :: "r"(smem_dst), "l"(gmem_src));
}
__device__ __forceinline__ void ldsm_x4(uint32_t& r0, uint32_t& r1, uint32_t& r2, uint32_t& r3,
                                        uint32_t saddr) {
    asm volatile("ldmatrix.sync.aligned.m8n8.x4.shared.b16 {%0,%1,%2,%3}, [%4];"
                 : "=r"(r0), "=r"(r1), "=r"(r2), "=r"(r3) : "r"(saddr));
}
__device__ __forceinline__ float warp_sum(float v) {
    v += __shfl_xor_sync(0xffffffffu, v, 16);
    v += __shfl_xor_sync(0xffffffffu, v, 8);
    v += __shfl_xor_sync(0xffffffffu, v, 4);
    v += __shfl_xor_sync(0xffffffffu, v, 2);
    v += __shfl_xor_sync(0xffffffffu, v, 1);
    return v;
}

// ---------------- K0: fp16 weight assembly ---------------------------------
__global__ void prep_kernel(const float* __restrict__ Wq, const float* __restrict__ Wk,
                            const float* __restrict__ Wg, const float* __restrict__ Wo) {
    int j = blockIdx.x;
    int e = threadIdx.x;
    if (j < 64)        g_WTh[j * 256 + e] = __float2half_rn(Wq[j * 256 + e]);
    else if (j < 128)  g_WTh[j * 256 + e] = __float2half_rn(Wk[(j - 64) * 256 + e]);
    else if (j < 384)  g_WTh[j * 256 + e] = __float2half_rn(Wg[(j - 128) * 256 + e]);
    else if (j < 640)  g_WTh[j * 256 + e] = __float2half_rn(Wo[(j - 384) * 512 + e]);
    else               g_W2h[(j - 640) * 256 + e] = __float2half_rn(Wo[(j - 640) * 512 + 256 + e]);
}

// ---------------- K0b: fp16 embedding copy ---------------------------------
__global__ void emb_cvt_kernel(const float* __restrict__ e) {
    size_t i = ((size_t)blockIdx.x * 256 + threadIdx.x) * 8;   // 8 elems/thread
    float4 f0 = *(const float4*)(e + i);
    float4 f1 = *(const float4*)(e + i + 4);
    __half2 h[4];
    h[0] = __floats2half2_rn(f0.x, f0.y);
    h[1] = __floats2half2_rn(f0.z, f0.w);
    h[2] = __floats2half2_rn(f1.x, f1.y);
    h[3] = __floats2half2_rn(f1.z, f1.w);
    *(uint4*)(g_embh + i) = *(uint4*)h;
}

// ---------------- GEMM template (fp16 m16n8k16, 2-stage cp.async) ----------
// MODE 0: A = g_embh (contiguous), B = g_WTh slab -> g_T (+ fp16 ke copy)
// MODE 1: A = g_ctxh, B = g_W2h -> + E1(table) + center, fused LN -> out
template <int MODE, int BROWS, int NTH>
__global__ __launch_bounds__(NTH, (NTH == 512) ? 1 : 2)
void gemm_kernel(const float* __restrict__ all_embs,
                 const int* __restrict__ center_idx,
                 const float* __restrict__ bg,
                 const float* __restrict__ bo,
                 const float* __restrict__ gamma,
                 const float* __restrict__ beta,
                 float* __restrict__ out) {
    constexpr int STAGE_BYTES = (128 + BROWS) * RPITCH;
    extern __shared__ char sm[];
    __shared__ int   ridx[128];
    __shared__ float redS[128][4];
    __shared__ float redQ[128][4];

    const int t    = threadIdx.x;
    const int lane = t & 31;
    const int warp = t >> 5;
    const int m0 = blockIdx.x * 128;
    const int n0 = blockIdx.y * BROWS;
    const __half* Bmat = (MODE == 0) ? (g_WTh + (size_t)n0 * 256) : g_W2h;

    if (MODE == 1 && t < 128) ridx[t] = center_idx[m0 + t];
    __syncthreads();

    const uint32_t sm_u32 = (uint32_t)__cvta_generic_to_shared(sm);
    const int g   = lane >> 2;
    const int tg  = lane & 3;
    const int mb  = (warp & 3) * 32;
    const int nbo = (warp >> 2) * 64;

    uint32_t a_off[2], b_off[4];
#pragma unroll
    for (int mt = 0; mt < 2; mt++)
        a_off[mt] = (mb + mt * 16 + (lane & 15)) * RPITCH + ((lane >> 4) & 1) * 16;
#pragma unroll
    for (int p = 0; p < 4; p++)
        b_off[p] = A_BYTES + (nbo + p * 16 + ((lane >> 4) & 1) * 8 + (lane & 7)) * RPITCH
                   + ((lane >> 3) & 1) * 16;

    auto load_stage = [&](int kt, int s) {
        const uint32_t dst0 = sm_u32 + s * STAGE_BYTES;
        const int kk = kt * 64;                      // halfs
        for (int idx = t; idx < 128 * 8; idx += NTH) {
            int row = idx >> 3, ch = idx & 7;
            const __half* src;
            if (MODE == 0) {
                int r = m0 + row; if (r >= NEMB) r = NEMB - 1;
                src = g_embh + (size_t)r * 256 + kk + ch * 8;
            } else {
                src = g_ctxh + (size_t)(m0 + row) * 256 + kk + ch * 8;
            }
            cp_async16(dst0 + row * RPITCH + ch * 16, src);
        }
        for (int idx = t; idx < BROWS * 8; idx += NTH) {
            int row = idx >> 3, ch = idx & 7;
            cp_async16(dst0 + A_BYTES + row * RPITCH + ch * 16,
                       Bmat + (size_t)row * 256 + kk + ch * 8);
        }
    };

    float acc[2][8][4] = {};
    uint32_t af[2][2][4];
    uint32_t bf[2][8][2];

    auto load_frags = [&](uint32_t stage, int ks, int buf) {
        const uint32_t kbyte = ks * 32;              // 16 halfs
#pragma unroll
        for (int mt = 0; mt < 2; mt++)
            ldsm_x4(af[buf][mt][0], af[buf][mt][1], af[buf][mt][2], af[buf][mt][3],
                    stage + a_off[mt] + kbyte);
#pragma unroll
        for (int p = 0; p < 4; p++)
            ldsm_x4(bf[buf][2 * p][0], bf[buf][2 * p][1], bf[buf][2 * p + 1][0],
                    bf[buf][2 * p + 1][1], stage + b_off[p] + kbyte);
    };

    load_stage(0, 0);
    asm volatile("cp.async.commit_group;\n" ::: "memory");

#pragma unroll 1
    for (int it = 0; it < 4; ++it) {
        const int s = it & 1;
        asm volatile("cp.async.wait_group 0;\n" ::: "memory");
        __syncthreads();
        if (it + 1 < 4) load_stage(it + 1, s ^ 1);
        asm volatile("cp.async.commit_group;\n" ::: "memory");

        const uint32_t stage = sm_u32 + s * STAGE_BYTES;
        load_frags(stage, 0, 0);
#pragma unroll
        for (int ks = 0; ks < 4; ks++) {
            const int cur = ks & 1;
            if (ks < 3) load_frags(stage, ks + 1, cur ^ 1);
#pragma unroll
            for (int mt = 0; mt < 2; mt++)
#pragma unroll
                for (int nt = 0; nt < 8; nt++)
                    asm volatile(
                        "mma.sync.aligned.m16n8k16.row.col.f32.f16.f16.f32 "
                        "{%0,%1,%2,%3}, {%4,%5,%6,%7}, {%8,%9}, {%0,%1,%2,%3};\n"
                        : "+f"(acc[mt][nt][0]), "+f"(acc[mt][nt][1]),
                          "+f"(acc[mt][nt][2]), "+f"(acc[mt][nt][3])
                        : "r"(af[cur][mt][0]), "r"(af[cur][mt][1]),
                          "r"(af[cur][mt][2]), "r"(af[cur][mt][3]),
                          "r"(bf[cur][nt][0]), "r"(bf[cur][nt][1]));
        }
    }

    if (MODE == 0) {
#pragma unroll
        for (int mt = 0; mt < 2; mt++)
#pragma unroll
            for (int nt = 0; nt < 8; nt++) {
                int j = n0 + nbo + nt * 8 + tg * 2;   // [0,640)
#pragma unroll
                for (int h = 0; h < 2; h++) {
                    int row = m0 + mb + mt * 16 + g + h * 8;
                    if (row >= NEMB) continue;
                    float v0 = acc[mt][nt][h * 2 + 0];
                    float v1 = acc[mt][nt][h * 2 + 1];
                    if (j >= 384) {
                        v0 += bo[j - 384];
                        v1 += bo[j - 383];
                    } else if (j >= 128) {
                        v0 = 1.f / (1.f + __expf(-(v0 + bg[j - 128])));
                        v1 = 1.f / (1.f + __expf(-(v1 + bg[j - 127])));
                    } else if (j >= 64) {
                        // ke region: also store fp16 copy for the neigh gather
                        *(__half2*)(g_keh + (size_t)row * 64 + (j - 64)) =
                            __floats2half2_rn(v0, v1);
                    }
                    *(float2*)(g_T + (size_t)row * 640 + j) = make_float2(v0, v1);
                }
            }
    } else {
        // MODE 1: + E1(table) + center, fused LayerNorm
        float rs[4] = {0.f, 0.f, 0.f, 0.f};
        float rq[4] = {0.f, 0.f, 0.f, 0.f};
#pragma unroll
        for (int mt = 0; mt < 2; mt++)
#pragma unroll
            for (int h = 0; h < 2; h++) {
                int lr = mb + mt * 16 + g + h * 8;
                const float* cen = all_embs + (size_t)ridx[lr] * 256;
                const float* e1r = g_T + (size_t)ridx[lr] * 640 + 384;
                float s = 0.f, q = 0.f;
#pragma unroll
                for (int nt = 0; nt < 8; nt++) {
                    int j = nbo + nt * 8 + tg * 2;
                    float2 e1 = *(const float2*)(e1r + j);
                    float2 c2 = *(const float2*)(cen + j);
                    float v0 = acc[mt][nt][h * 2 + 0] + e1.x + c2.x;
                    float v1 = acc[mt][nt][h * 2 + 1] + e1.y + c2.y;
                    acc[mt][nt][h * 2 + 0] = v0;
                    acc[mt][nt][h * 2 + 1] = v1;
                    s += v0 + v1;
                    q += v0 * v0 + v1 * v1;
                }
                rs[mt * 2 + h] = s;
                rq[mt * 2 + h] = q;
            }
#pragma unroll
        for (int i = 0; i < 4; i++) {
            rs[i] += __shfl_xor_sync(0xffffffffu, rs[i], 1);
            rs[i] += __shfl_xor_sync(0xffffffffu, rs[i], 2);
            rq[i] += __shfl_xor_sync(0xffffffffu, rq[i], 1);
            rq[i] += __shfl_xor_sync(0xffffffffu, rq[i], 2);
        }
        const int nw = warp >> 2;
        if (tg == 0) {
#pragma unroll
            for (int mt = 0; mt < 2; mt++)
#pragma unroll
                for (int h = 0; h < 2; h++) {
                    int lr = mb + mt * 16 + g + h * 8;
                    redS[lr][nw] = rs[mt * 2 + h];
                    redQ[lr][nw] = rq[mt * 2 + h];
                }
        }
        __syncthreads();
        float mu[4], rstd[4];
#pragma unroll
        for (int mt = 0; mt < 2; mt++)
#pragma unroll
            for (int h = 0; h < 2; h++) {
                int lr = mb + mt * 16 + g + h * 8;
                float s = redS[lr][0] + redS[lr][1] + redS[lr][2] + redS[lr][3];
                float q = redQ[lr][0] + redQ[lr][1] + redQ[lr][2] + redQ[lr][3];
                float m = s * (1.f / 256.f);
                float v = q * (1.f / 256.f) - m * m;
                mu[mt * 2 + h] = m;
                rstd[mt * 2 + h] = rsqrtf(v + 1e-5f);
            }
#pragma unroll
        for (int mt = 0; mt < 2; mt++)
#pragma unroll
            for (int nt = 0; nt < 8; nt++) {
                int j = nbo + nt * 8 + tg * 2;
                float2 gm = *(const float2*)(gamma + j);
                float2 bt = *(const float2*)(beta + j);
#pragma unroll
                for (int h = 0; h < 2; h++) {
                    int row = m0 + mb + mt * 16 + g + h * 8;
                    float m = mu[mt * 2 + h], r = rstd[mt * 2 + h];
                    float o0 = (acc[mt][nt][h * 2 + 0] - m) * r * gm.x + bt.x;
                    float o1 = (acc[mt][nt][h * 2 + 1] - m) * r * gm.y + bt.y;
                    *(float2*)(out + (size_t)row * 256 + j) = make_float2(o0, o1);
                }
            }
    }
}

// ---------------- neigh: streaming from fp16 sources ------------------------
// Per warp: 16 fp16 ke gathers (128B) -> logits; 16 fp16 row streams (512B)
// -> context; gate (fp32 table) multiply; fp16 ctx store.
__global__ __launch_bounds__(256)
void neigh_kernel(const int* __restrict__ center_idx,
                  const int* __restrict__ nb_idx,
                  const float* __restrict__ nb_w) {
    const int warp = threadIdx.x >> 5;
    const int lane = threadIdx.x & 31;
    const int b = blockIdx.x * 8 + warp;

    const int cidx = center_idx[b];
    const float* trow = g_T + (size_t)cidx * 640;
    const float2 q2 = *(const float2*)(trow + 2 * lane);   // q[2l], q[2l+1]

    int   myidx = 0;
    float myw   = 0.f;
    if (lane < 16) {
        myidx = nb_idx[b * 16 + lane];
        myw   = fmaxf(nb_w[b * 16 + lane], 1e-6f);
    }

    // logits: lane j keeps logit for neighbor j (j<16); ke fp16 gather
    float lgj = 0.f;
#pragma unroll
    for (int k = 0; k < 16; k++) {
        int r = __shfl_sync(0xffffffffu, myidx, k);
        float2 kf = __half22float2(*(const __half2*)(g_keh + (size_t)r * 64 + 2 * lane));
        float s = warp_sum(kf.x * q2.x + kf.y * q2.y);
        if (lane == k) lgj = s;
    }

    // softmax over 16 lanes (weights folded: w * exp(l - max))
    float l = (lane < 16) ? lgj * 0.125f : -1e30f;
    float mx = l;
#pragma unroll
    for (int off = 8; off >= 1; off >>= 1)
        mx = fmaxf(mx, __shfl_xor_sync(0xffffffffu, mx, off));
    float e = (lane < 16) ? myw * __expf(l - mx) : 0.f;
    float es = e;
#pragma unroll
    for (int off = 8; off >= 1; off >>= 1)
        es += __shfl_xor_sync(0xffffffffu, es, off);
    float ai = e / es;

    // context: stream fp16 neighbor rows once; lane covers cols [8l, 8l+8)
    float a[8] = {0, 0, 0, 0, 0, 0, 0, 0};
#pragma unroll
    for (int k = 0; k < 16; k++) {
        int   r  = __shfl_sync(0xffffffffu, myidx, k);
        float ak = __shfl_sync(0xffffffffu, ai, k);
        uint4 v = *(const uint4*)(g_embh + (size_t)r * 256 + lane * 8);
        const __half2* hp = (const __half2*)&v;
#pragma unroll
        for (int u = 0; u < 4; u++) {
            float2 f = __half22float2(hp[u]);
            a[2 * u + 0] = fmaf(ak, f.x, a[2 * u + 0]);
            a[2 * u + 1] = fmaf(ak, f.y, a[2 * u + 1]);
        }
    }

    // gate multiply (fp32 table) and fp16 store
    float4 g0 = *(const float4*)(trow + 128 + lane * 8);
    float4 g1 = *(const float4*)(trow + 128 + lane * 8 + 4);
    __half2 h[4];
    h[0] = __floats2half2_rn(g0.x * a[0], g0.y * a[1]);
    h[1] = __floats2half2_rn(g0.z * a[2], g0.w * a[3]);
    h[2] = __floats2half2_rn(g1.x * a[4], g1.y * a[5]);
    h[3] = __floats2half2_rn(g1.z * a[6], g1.w * a[7]);
    *(uint4*)(g_ctxh + (size_t)b * 256 + lane * 8) = *(uint4*)h;
}

// ---------------- launch ---------------------------------------------------
extern "C" void kernel_launch(void* const* d_in, const int* in_sizes, int n_in,
                              void* d_out, int out_size) {
    const float* all_embs   = (const float*)d_in[0];
    const int*   center_idx = (const int*)d_in[1];
    const int*   nb_idx     = (const int*)d_in[2];
    const float* nb_w       = (const float*)d_in[3];
    const float* Wq         = (const float*)d_in[4];
    const float* Wk         = (const float*)d_in[5];
    const float* Wg         = (const float*)d_in[6];
    const float* bg         = (const float*)d_in[7];
    const float* Wo         = (const float*)d_in[8];
    const float* bo         = (const float*)d_in[9];
    const float* gamma      = (const float*)d_in[10];
    const float* beta       = (const float*)d_in[11];
    float* out = (float*)d_out;

    const int sm128 = 2 * (128 + 128) * RPITCH;   // 73728
    const int sm256 = 2 * (128 + 256) * RPITCH;   // 110592

    static int configured = 0;
    if (!configured) {
        cudaFuncSetAttribute((const void*)gemm_kernel<0, 128, 256>,
                             cudaFuncAttributeMaxDynamicSharedMemorySize, sm128);
        cudaFuncSetAttribute((const void*)gemm_kernel<1, 256, 512>,
                             cudaFuncAttributeMaxDynamicSharedMemorySize, sm256);
        configured = 1;
    }

    prep_kernel<<<896, 256>>>(Wq, Wk, Wg, Wo);
    emb_cvt_kernel<<<2500, 256>>>(all_embs);
    gemm_kernel<0, 128, 256><<<dim3((NEMB + 127) / 128, 5), 256, sm128>>>(
        all_embs, center_idx, bg, bo, gamma, beta, nullptr);                 // table q|ke|gate|E1
    neigh_kernel<<<BATCH / 8, 256>>>(center_idx, nb_idx, nb_w);
    gemm_kernel<1, 256, 512><<<dim3(BATCH / 128, 1), 512, sm256>>>(
        all_embs, center_idx, bg, bo, gamma, beta, out);                     // out + LN
}

// round 12
// speedup vs baseline: 2.3993x; 1.0588x over previous
#include <cuda_runtime.h>
#include <cuda_fp16.h>
#include <cstdint>

#define BATCH 32768
#define NEMB  20000
#define RPITCH 144                 // bytes per smem row (64 halfs used + pad)
#define A_BYTES (128 * RPITCH)

// ---------------- device scratch (static, allocation-free) ----------------
__device__ __align__(128) __half g_WTh[640 * 256];           // Wq|Wk|Wg|Wo1 rows (fp16)
__device__ __align__(128) __half g_W2h[256 * 256];           // Wo2 (fp16)
__device__ __align__(128) __half g_embh[(size_t)NEMB * 256]; // fp16 embedding copy
__device__ __align__(128) __half g_qh[(size_t)NEMB * 64];    // fp16 q table
__device__ __align__(128) __half g_keh[(size_t)NEMB * 64];   // fp16 ke table
__device__ __align__(128) __half g_gateh[(size_t)NEMB * 256];// fp16 gate table
__device__ __align__(128) float  g_E1[(size_t)NEMB * 256];   // fp32 E1 table
__device__ __align__(128) __half g_ctxh[(size_t)BATCH * 256];// gated context (fp16)

__device__ __forceinline__ void cp_async16(uint32_t smem_dst, const void* gmem_src) {
    asm volatile("cp.async.cg.shared.global [%0], [%1], 16;\n" :: "r"(smem_dst), "l"(gmem_src));
}
__device__ __forceinline__ void ldsm_x4(uint32_t& r0, uint32_t& r1, uint32_t& r2, uint32_t& r3,
                                        uint32_t saddr) {
    asm volatile("ldmatrix.sync.aligned.m8n8.x4.shared.b16 {%0,%1,%2,%3}, [%4];"
                 : "=r"(r0), "=r"(r1), "=r"(r2), "=r"(r3) : "r"(saddr));
}

// ---------------- K0: fp16 weight assembly ---------------------------------
__global__ void prep_kernel(const float* __restrict__ Wq, const float* __restrict__ Wk,
                            const float* __restrict__ Wg, const float* __restrict__ Wo) {
    int j = blockIdx.x;
    int e = threadIdx.x;
    if (j < 64)        g_WTh[j * 256 + e] = __float2half_rn(Wq[j * 256 + e]);
    else if (j < 128)  g_WTh[j * 256 + e] = __float2half_rn(Wk[(j - 64) * 256 + e]);
    else if (j < 384)  g_WTh[j * 256 + e] = __float2half_rn(Wg[(j - 128) * 256 + e]);
    else if (j < 640)  g_WTh[j * 256 + e] = __float2half_rn(Wo[(j - 384) * 512 + e]);
    else               g_W2h[(j - 640) * 256 + e] = __float2half_rn(Wo[(j - 640) * 512 + 256 + e]);
}

// ---------------- K0b: fp16 embedding copy ---------------------------------
__global__ void emb_cvt_kernel(const float* __restrict__ e) {
    size_t i = ((size_t)blockIdx.x * 256 + threadIdx.x) * 8;   // 8 elems/thread
    float4 f0 = *(const float4*)(e + i);
    float4 f1 = *(const float4*)(e + i + 4);
    __half2 h[4];
    h[0] = __floats2half2_rn(f0.x, f0.y);
    h[1] = __floats2half2_rn(f0.z, f0.w);
    h[2] = __floats2half2_rn(f1.x, f1.y);
    h[3] = __floats2half2_rn(f1.z, f1.w);
    *(uint4*)(g_embh + i) = *(uint4*)h;
}

// ---------------- GEMM template (fp16 m16n8k16, 2-stage cp.async) ----------
// MODE 0: A = g_embh (contiguous), B = g_WTh slab -> fp16 q/ke/gate + fp32 E1
// MODE 1: A = g_ctxh, B = g_W2h -> + E1(table) + center, fused LN -> out
template <int MODE, int BROWS, int NTH>
__global__ __launch_bounds__(NTH, (NTH == 512) ? 1 : 2)
void gemm_kernel(const float* __restrict__ all_embs,
                 const int* __restrict__ center_idx,
                 const float* __restrict__ bg,
                 const float* __restrict__ bo,
                 const float* __restrict__ gamma,
                 const float* __restrict__ beta,
                 float* __restrict__ out) {
    constexpr int STAGE_BYTES = (128 + BROWS) * RPITCH;
    extern __shared__ char sm[];
    __shared__ int   ridx[128];
    __shared__ float redS[128][4];
    __shared__ float redQ[128][4];

    const int t    = threadIdx.x;
    const int lane = t & 31;
    const int warp = t >> 5;
    const int m0 = blockIdx.x * 128;
    const int n0 = blockIdx.y * BROWS;
    const __half* Bmat = (MODE == 0) ? (g_WTh + (size_t)n0 * 256) : g_W2h;

    if (MODE == 1 && t < 128) ridx[t] = center_idx[m0 + t];
    __syncthreads();

    const uint32_t sm_u32 = (uint32_t)__cvta_generic_to_shared(sm);
    const int g   = lane >> 2;
    const int tg  = lane & 3;
    const int mb  = (warp & 3) * 32;
    const int nbo = (warp >> 2) * 64;

    uint32_t a_off[2], b_off[4];
#pragma unroll
    for (int mt = 0; mt < 2; mt++)
        a_off[mt] = (mb + mt * 16 + (lane & 15)) * RPITCH + ((lane >> 4) & 1) * 16;
#pragma unroll
    for (int p = 0; p < 4; p++)
        b_off[p] = A_BYTES + (nbo + p * 16 + ((lane >> 4) & 1) * 8 + (lane & 7)) * RPITCH
                   + ((lane >> 3) & 1) * 16;

    auto load_stage = [&](int kt, int s) {
        const uint32_t dst0 = sm_u32 + s * STAGE_BYTES;
        const int kk = kt * 64;                      // halfs
        for (int idx = t; idx < 128 * 8; idx += NTH) {
            int row = idx >> 3, ch = idx & 7;
            const __half* src;
            if (MODE == 0) {
                int r = m0 + row; if (r >= NEMB) r = NEMB - 1;
                src = g_embh + (size_t)r * 256 + kk + ch * 8;
            } else {
                src = g_ctxh + (size_t)(m0 + row) * 256 + kk + ch * 8;
            }
            cp_async16(dst0 + row * RPITCH + ch * 16, src);
        }
        for (int idx = t; idx < BROWS * 8; idx += NTH) {
            int row = idx >> 3, ch = idx & 7;
            cp_async16(dst0 + A_BYTES + row * RPITCH + ch * 16,
                       Bmat + (size_t)row * 256 + kk + ch * 8);
        }
    };

    float acc[2][8][4] = {};
    uint32_t af[2][2][4];
    uint32_t bf[2][8][2];

    auto load_frags = [&](uint32_t stage, int ks, int buf) {
        const uint32_t kbyte = ks * 32;              // 16 halfs
#pragma unroll
        for (int mt = 0; mt < 2; mt++)
            ldsm_x4(af[buf][mt][0], af[buf][mt][1], af[buf][mt][2], af[buf][mt][3],
                    stage + a_off[mt] + kbyte);
#pragma unroll
        for (int p = 0; p < 4; p++)
            ldsm_x4(bf[buf][2 * p][0], bf[buf][2 * p][1], bf[buf][2 * p + 1][0],
                    bf[buf][2 * p + 1][1], stage + b_off[p] + kbyte);
    };

    load_stage(0, 0);
    asm volatile("cp.async.commit_group;\n" ::: "memory");

#pragma unroll 1
    for (int it = 0; it < 4; ++it) {
        const int s = it & 1;
        asm volatile("cp.async.wait_group 0;\n" ::: "memory");
        __syncthreads();
        if (it + 1 < 4) load_stage(it + 1, s ^ 1);
        asm volatile("cp.async.commit_group;\n" ::: "memory");

        const uint32_t stage = sm_u32 + s * STAGE_BYTES;
        load_frags(stage, 0, 0);
#pragma unroll
        for (int ks = 0; ks < 4; ks++) {
            const int cur = ks & 1;
            if (ks < 3) load_frags(stage, ks + 1, cur ^ 1);
#pragma unroll
            for (int mt = 0; mt < 2; mt++)
#pragma unroll
                for (int nt = 0; nt < 8; nt++)
                    asm volatile(
                        "mma.sync.aligned.m16n8k16.row.col.f32.f16.f16.f32 "
                        "{%0,%1,%2,%3}, {%4,%5,%6,%7}, {%8,%9}, {%0,%1,%2,%3};\n"
                        : "+f"(acc[mt][nt][0]), "+f"(acc[mt][nt][1]),
                          "+f"(acc[mt][nt][2]), "+f"(acc[mt][nt][3])
                        : "r"(af[cur][mt][0]), "r"(af[cur][mt][1]),
                          "r"(af[cur][mt][2]), "r"(af[cur][mt][3]),
                          "r"(bf[cur][nt][0]), "r"(bf[cur][nt][1]));
        }
    }

    if (MODE == 0) {
#pragma unroll
        for (int mt = 0; mt < 2; mt++)
#pragma unroll
            for (int nt = 0; nt < 8; nt++) {
                int j = n0 + nbo + nt * 8 + tg * 2;   // [0,640)
#pragma unroll
                for (int h = 0; h < 2; h++) {
                    int row = m0 + mb + mt * 16 + g + h * 8;
                    if (row >= NEMB) continue;
                    float v0 = acc[mt][nt][h * 2 + 0];
                    float v1 = acc[mt][nt][h * 2 + 1];
                    if (j < 64) {
                        *(__half2*)(g_qh + (size_t)row * 64 + j) = __floats2half2_rn(v0, v1);
                    } else if (j < 128) {
                        *(__half2*)(g_keh + (size_t)row * 64 + (j - 64)) = __floats2half2_rn(v0, v1);
                    } else if (j < 384) {
                        v0 = 1.f / (1.f + __expf(-(v0 + bg[j - 128])));
                        v1 = 1.f / (1.f + __expf(-(v1 + bg[j - 127])));
                        *(__half2*)(g_gateh + (size_t)row * 256 + (j - 128)) = __floats2half2_rn(v0, v1);
                    } else {
                        v0 += bo[j - 384];
                        v1 += bo[j - 383];
                        *(float2*)(g_E1 + (size_t)row * 256 + (j - 384)) = make_float2(v0, v1);
                    }
                }
            }
    } else {
        // MODE 1: + E1(table) + center, fused LayerNorm
        float rs[4] = {0.f, 0.f, 0.f, 0.f};
        float rq[4] = {0.f, 0.f, 0.f, 0.f};
#pragma unroll
        for (int mt = 0; mt < 2; mt++)
#pragma unroll
            for (int h = 0; h < 2; h++) {
                int lr = mb + mt * 16 + g + h * 8;
                const float* cen = all_embs + (size_t)ridx[lr] * 256;
                const float* e1r = g_E1 + (size_t)ridx[lr] * 256;
                float s = 0.f, q = 0.f;
#pragma unroll
                for (int nt = 0; nt < 8; nt++) {
                    int j = nbo + nt * 8 + tg * 2;
                    float2 e1 = *(const float2*)(e1r + j);
                    float2 c2 = *(const float2*)(cen + j);
                    float v0 = acc[mt][nt][h * 2 + 0] + e1.x + c2.x;
                    float v1 = acc[mt][nt][h * 2 + 1] + e1.y + c2.y;
                    acc[mt][nt][h * 2 + 0] = v0;
                    acc[mt][nt][h * 2 + 1] = v1;
                    s += v0 + v1;
                    q += v0 * v0 + v1 * v1;
                }
                rs[mt * 2 + h] = s;
                rq[mt * 2 + h] = q;
            }
#pragma unroll
        for (int i = 0; i < 4; i++) {
            rs[i] += __shfl_xor_sync(0xffffffffu, rs[i], 1);
            rs[i] += __shfl_xor_sync(0xffffffffu, rs[i], 2);
            rq[i] += __shfl_xor_sync(0xffffffffu, rq[i], 1);
            rq[i] += __shfl_xor_sync(0xffffffffu, rq[i], 2);
        }
        const int nw = warp >> 2;
        if (tg == 0) {
#pragma unroll
            for (int mt = 0; mt < 2; mt++)
#pragma unroll
                for (int h = 0; h < 2; h++) {
                    int lr = mb + mt * 16 + g + h * 8;
                    redS[lr][nw] = rs[mt * 2 + h];
                    redQ[lr][nw] = rq[mt * 2 + h];
                }
        }
        __syncthreads();
        float mu[4], rstd[4];
#pragma unroll
        for (int mt = 0; mt < 2; mt++)
#pragma unroll
            for (int h = 0; h < 2; h++) {
                int lr = mb + mt * 16 + g + h * 8;
                float s = redS[lr][0] + redS[lr][1] + redS[lr][2] + redS[lr][3];
                float q = redQ[lr][0] + redQ[lr][1] + redQ[lr][2] + redQ[lr][3];
                float m = s * (1.f / 256.f);
                float v = q * (1.f / 256.f) - m * m;
                mu[mt * 2 + h] = m;
                rstd[mt * 2 + h] = rsqrtf(v + 1e-5f);
            }
#pragma unroll
        for (int mt = 0; mt < 2; mt++)
#pragma unroll
            for (int nt = 0; nt < 8; nt++) {
                int j = nbo + nt * 8 + tg * 2;
                float2 gm = *(const float2*)(gamma + j);
                float2 bt = *(const float2*)(beta + j);
#pragma unroll
                for (int h = 0; h < 2; h++) {
                    int row = m0 + mb + mt * 16 + g + h * 8;
                    float m = mu[mt * 2 + h], r = rstd[mt * 2 + h];
                    float o0 = (acc[mt][nt][h * 2 + 0] - m) * r * gm.x + bt.x;
                    float o1 = (acc[mt][nt][h * 2 + 1] - m) * r * gm.y + bt.y;
                    *(float2*)(out + (size_t)row * 256 + j) = make_float2(o0, o1);
                }
            }
    }
}

// ---------------- neigh: group-parallel logits + streamed context ----------
// Warp = 4 groups of 8 lanes. Pass p: group grp computes logit of neighbor
// 4p+grp (uint4 ke load, 8 fma, 3-shfl butterfly). 16 shfl total vs 80.
__global__ __launch_bounds__(256)
void neigh_kernel(const int* __restrict__ center_idx,
                  const int* __restrict__ nb_idx,
                  const float* __restrict__ nb_w) {
    const int warp = threadIdx.x >> 5;
    const int lane = threadIdx.x & 31;
    const int b = blockIdx.x * 8 + warp;
    const int grp = lane >> 3;
    const int u   = lane & 7;

    const int cidx = center_idx[b];

    // q fragment: dims [8u, 8u+8)
    uint4 qv = *(const uint4*)(g_qh + (size_t)cidx * 64 + u * 8);
    const __half2* qh = (const __half2*)&qv;
    float2 qf[4];
#pragma unroll
    for (int i = 0; i < 4; i++) qf[i] = __half22float2(qh[i]);

    int   myidx = 0;
    float myw   = 0.f;
    if (lane < 16) {
        myidx = nb_idx[b * 16 + lane];
        myw   = fmaxf(nb_w[b * 16 + lane], 1e-6f);
    }

    // group-parallel logits
    float v[4];
#pragma unroll
    for (int p = 0; p < 4; p++) {
        int r = __shfl_sync(0xffffffffu, myidx, p * 4 + grp);
        uint4 kv = *(const uint4*)(g_keh + (size_t)r * 64 + u * 8);
        const __half2* kh = (const __half2*)&kv;
        float s = 0.f;
#pragma unroll
        for (int i = 0; i < 4; i++) {
            float2 kf = __half22float2(kh[i]);
            s = fmaf(kf.x, qf[i].x, s);
            s = fmaf(kf.y, qf[i].y, s);
        }
        s += __shfl_xor_sync(0xffffffffu, s, 1);
        s += __shfl_xor_sync(0xffffffffu, s, 2);
        s += __shfl_xor_sync(0xffffffffu, s, 4);
        v[p] = s;
    }
    // collect: lane j (<16) wants v[j>>2] from lane (j&3)*8
    const int src = (lane & 3) * 8;
    float t0 = __shfl_sync(0xffffffffu, v[0], src);
    float t1 = __shfl_sync(0xffffffffu, v[1], src);
    float t2 = __shfl_sync(0xffffffffu, v[2], src);
    float t3 = __shfl_sync(0xffffffffu, v[3], src);
    const int sel = lane >> 2;
    float lgj = (sel == 0) ? t0 : (sel == 1) ? t1 : (sel == 2) ? t2 : t3;

    // softmax over 16 lanes (weights folded: w * exp(l - max))
    float l = (lane < 16) ? lgj * 0.125f : -1e30f;
    float mx = l;
#pragma unroll
    for (int off = 8; off >= 1; off >>= 1)
        mx = fmaxf(mx, __shfl_xor_sync(0xffffffffu, mx, off));
    float e = (lane < 16) ? myw * __expf(l - mx) : 0.f;
    float es = e;
#pragma unroll
    for (int off = 8; off >= 1; off >>= 1)
        es += __shfl_xor_sync(0xffffffffu, es, off);
    float ai = e / es;

    // context: stream fp16 neighbor rows once; lane covers cols [8l, 8l+8)
    float a[8] = {0, 0, 0, 0, 0, 0, 0, 0};
#pragma unroll
    for (int k = 0; k < 16; k++) {
        int   r  = __shfl_sync(0xffffffffu, myidx, k);
        float ak = __shfl_sync(0xffffffffu, ai, k);
        uint4 nv = *(const uint4*)(g_embh + (size_t)r * 256 + lane * 8);
        const __half2* hp = (const __half2*)&nv;
#pragma unroll
        for (int i = 0; i < 4; i++) {
            float2 f = __half22float2(hp[i]);
            a[2 * i + 0] = fmaf(ak, f.x, a[2 * i + 0]);
            a[2 * i + 1] = fmaf(ak, f.y, a[2 * i + 1]);
        }
    }

    // gate (fp16 table) multiply, fp16 store
    uint4 gv = *(const uint4*)(g_gateh + (size_t)cidx * 256 + lane * 8);
    const __half2* gh = (const __half2*)&gv;
    __half2 hout[4];
#pragma unroll
    for (int i = 0; i < 4; i++) {
        float2 gf = __half22float2(gh[i]);
        hout[i] = __floats2half2_rn(gf.x * a[2 * i + 0], gf.y * a[2 * i + 1]);
    }
    *(uint4*)(g_ctxh + (size_t)b * 256 + lane * 8) = *(uint4*)hout;
}

// ---------------- launch ---------------------------------------------------
extern "C" void kernel_launch(void* const* d_in, const int* in_sizes, int n_in,
                              void* d_out, int out_size) {
    const float* all_embs   = (const float*)d_in[0];
    const int*   center_idx = (const int*)d_in[1];
    const int*   nb_idx     = (const int*)d_in[2];
    const float* nb_w       = (const float*)d_in[3];
    const float* Wq         = (const float*)d_in[4];
    const float* Wk         = (const float*)d_in[5];
    const float* Wg         = (const float*)d_in[6];
    const float* bg         = (const float*)d_in[7];
    const float* Wo         = (const float*)d_in[8];
    const float* bo         = (const float*)d_in[9];
    const float* gamma      = (const float*)d_in[10];
    const float* beta       = (const float*)d_in[11];
    float* out = (float*)d_out;

    const int sm128 = 2 * (128 + 128) * RPITCH;   // 73728
    const int sm256 = 2 * (128 + 256) * RPITCH;   // 110592

    static int configured = 0;
    if (!configured) {
        cudaFuncSetAttribute((const void*)gemm_kernel<0, 128, 256>,
                             cudaFuncAttributeMaxDynamicSharedMemorySize, sm128);
        cudaFuncSetAttribute((const void*)gemm_kernel<1, 256, 512>,
                             cudaFuncAttributeMaxDynamicSharedMemorySize, sm256);
        configured = 1;
    }

    prep_kernel<<<896, 256>>>(Wq, Wk, Wg, Wo);
    emb_cvt_kernel<<<2500, 256>>>(all_embs);
    gemm_kernel<0, 128, 256><<<dim3((NEMB + 127) / 128, 5), 256, sm128>>>(
        all_embs, center_idx, bg, bo, gamma, beta, nullptr);                 // tables q|ke|gate|E1
    neigh_kernel<<<BATCH / 8, 256>>>(center_idx, nb_idx, nb_w);
    gemm_kernel<1, 256, 512><<<dim3(BATCH / 128, 1), 512, sm256>>>(
        all_embs, center_idx, bg, bo, gamma, beta, out);                     // out + LN
}

// round 13
// speedup vs baseline: 2.4942x; 1.0396x over previous
#include <cuda_runtime.h>
#include <cuda_fp16.h>
#include <cstdint>

#define BATCH 32768
#define NEMB  20000
#define RPITCH 144                 // bytes per smem row (64 halfs used + pad)
#define A_BYTES (128 * RPITCH)

// ---------------- device scratch (static, allocation-free) ----------------
__device__ __align__(128) __half g_WTh[640 * 256];           // Wq|Wk|Wg|Wo1 rows (fp16)
__device__ __align__(128) __half g_W2h[256 * 256];           // Wo2 (fp16)
__device__ __align__(128) __half g_embh[(size_t)NEMB * 256]; // fp16 embedding copy
__device__ __align__(128) __half g_qh[(size_t)NEMB * 64];    // fp16 q table
__device__ __align__(128) __half g_keh[(size_t)NEMB * 64];   // fp16 ke table
__device__ __align__(128) __half g_gateh[(size_t)NEMB * 256];// fp16 gate table
__device__ __align__(128) float  g_E1[(size_t)NEMB * 256];   // fp32 E1 table
__device__ __align__(128) __half g_ctxh[(size_t)BATCH * 256];// gated context (fp16)

__device__ __forceinline__ void cp_async16(uint32_t smem_dst, const void* gmem_src) {
    asm volatile("cp.async.cg.shared.global [%0], [%1], 16;\n" :: "r"(smem_dst), "l"(gmem_src));
}
__device__ __forceinline__ void ldsm_x4(uint32_t& r0, uint32_t& r1, uint32_t& r2, uint32_t& r3,
                                        uint32_t saddr) {
    asm volatile("ldmatrix.sync.aligned.m8n8.x4.shared.b16 {%0,%1,%2,%3}, [%4];"
                 : "=r"(r0), "=r"(r1), "=r"(r2), "=r"(r3) : "r"(saddr));
}

// ---------------- K0: fp16 weight assembly + fp16 embedding copy -----------
__global__ void prep_kernel(const float* __restrict__ Wq, const float* __restrict__ Wk,
                            const float* __restrict__ Wg, const float* __restrict__ Wo,
                            const float* __restrict__ embs) {
    int j = blockIdx.x;
    int e = threadIdx.x;
    if (j < 64)        g_WTh[j * 256 + e] = __float2half_rn(Wq[j * 256 + e]);
    else if (j < 128)  g_WTh[j * 256 + e] = __float2half_rn(Wk[(j - 64) * 256 + e]);
    else if (j < 384)  g_WTh[j * 256 + e] = __float2half_rn(Wg[(j - 128) * 256 + e]);
    else if (j < 640)  g_WTh[j * 256 + e] = __float2half_rn(Wo[(j - 384) * 512 + e]);
    else if (j < 896)  g_W2h[(j - 640) * 256 + e] = __float2half_rn(Wo[(j - 640) * 512 + 256 + e]);
    else {
        // embedding convert: blocks [896, 896+2500)
        size_t i = ((size_t)(j - 896) * 256 + e) * 8;
        float4 f0 = *(const float4*)(embs + i);
        float4 f1 = *(const float4*)(embs + i + 4);
        __half2 h[4];
        h[0] = __floats2half2_rn(f0.x, f0.y);
        h[1] = __floats2half2_rn(f0.z, f0.w);
        h[2] = __floats2half2_rn(f1.x, f1.y);
        h[3] = __floats2half2_rn(f1.z, f1.w);
        *(uint4*)(g_embh + i) = *(uint4*)h;
    }
}

// ---------------- GEMM template (fp16 m16n8k16, 2-stage cp.async) ----------
// MODE 0: A = g_embh (contiguous), B = g_WTh slab -> fp16 q/ke/gate + fp32 E1
// MODE 1: A = g_ctxh, B = g_W2h -> + E1(table) + center, fused LN -> out
template <int MODE, int BROWS, int NTH>
__global__ __launch_bounds__(NTH, (NTH == 512) ? 1 : 2)
void gemm_kernel(const float* __restrict__ all_embs,
                 const int* __restrict__ center_idx,
                 const float* __restrict__ bg,
                 const float* __restrict__ bo,
                 const float* __restrict__ gamma,
                 const float* __restrict__ beta,
                 float* __restrict__ out) {
    constexpr int STAGE_BYTES = (128 + BROWS) * RPITCH;
    extern __shared__ char sm[];
    __shared__ int   ridx[128];
    __shared__ float redS[128][4];
    __shared__ float redQ[128][4];

    const int t    = threadIdx.x;
    const int lane = t & 31;
    const int warp = t >> 5;
    const int m0 = blockIdx.x * 128;
    const int n0 = blockIdx.y * BROWS;
    const __half* Bmat = (MODE == 0) ? (g_WTh + (size_t)n0 * 256) : g_W2h;

    if (MODE == 1 && t < 128) ridx[t] = center_idx[m0 + t];
    __syncthreads();

    const uint32_t sm_u32 = (uint32_t)__cvta_generic_to_shared(sm);
    const int g   = lane >> 2;
    const int tg  = lane & 3;
    const int mb  = (warp & 3) * 32;
    const int nbo = (warp >> 2) * 64;

    uint32_t a_off[2], b_off[4];
#pragma unroll
    for (int mt = 0; mt < 2; mt++)
        a_off[mt] = (mb + mt * 16 + (lane & 15)) * RPITCH + ((lane >> 4) & 1) * 16;
#pragma unroll
    for (int p = 0; p < 4; p++)
        b_off[p] = A_BYTES + (nbo + p * 16 + ((lane >> 4) & 1) * 8 + (lane & 7)) * RPITCH
                   + ((lane >> 3) & 1) * 16;

    auto load_stage = [&](int kt, int s) {
        const uint32_t dst0 = sm_u32 + s * STAGE_BYTES;
        const int kk = kt * 64;                      // halfs
        for (int idx = t; idx < 128 * 8; idx += NTH) {
            int row = idx >> 3, ch = idx & 7;
            const __half* src;
            if (MODE == 0) {
                int r = m0 + row; if (r >= NEMB) r = NEMB - 1;
                src = g_embh + (size_t)r * 256 + kk + ch * 8;
            } else {
                src = g_ctxh + (size_t)(m0 + row) * 256 + kk + ch * 8;
            }
            cp_async16(dst0 + row * RPITCH + ch * 16, src);
        }
        for (int idx = t; idx < BROWS * 8; idx += NTH) {
            int row = idx >> 3, ch = idx & 7;
            cp_async16(dst0 + A_BYTES + row * RPITCH + ch * 16,
                       Bmat + (size_t)row * 256 + kk + ch * 8);
        }
    };

    float acc[2][8][4] = {};
    uint32_t af[2][2][4];
    uint32_t bf[2][8][2];

    auto load_frags = [&](uint32_t stage, int ks, int buf) {
        const uint32_t kbyte = ks * 32;              // 16 halfs
#pragma unroll
        for (int mt = 0; mt < 2; mt++)
            ldsm_x4(af[buf][mt][0], af[buf][mt][1], af[buf][mt][2], af[buf][mt][3],
                    stage + a_off[mt] + kbyte);
#pragma unroll
        for (int p = 0; p < 4; p++)
            ldsm_x4(bf[buf][2 * p][0], bf[buf][2 * p][1], bf[buf][2 * p + 1][0],
                    bf[buf][2 * p + 1][1], stage + b_off[p] + kbyte);
    };

    load_stage(0, 0);
    asm volatile("cp.async.commit_group;\n" ::: "memory");

#pragma unroll 1
    for (int it = 0; it < 4; ++it) {
        const int s = it & 1;
        asm volatile("cp.async.wait_group 0;\n" ::: "memory");
        __syncthreads();
        if (it + 1 < 4) load_stage(it + 1, s ^ 1);
        asm volatile("cp.async.commit_group;\n" ::: "memory");

        const uint32_t stage = sm_u32 + s * STAGE_BYTES;
        load_frags(stage, 0, 0);
#pragma unroll
        for (int ks = 0; ks < 4; ks++) {
            const int cur = ks & 1;
            if (ks < 3) load_frags(stage, ks + 1, cur ^ 1);
#pragma unroll
            for (int mt = 0; mt < 2; mt++)
#pragma unroll
                for (int nt = 0; nt < 8; nt++)
                    asm volatile(
                        "mma.sync.aligned.m16n8k16.row.col.f32.f16.f16.f32 "
                        "{%0,%1,%2,%3}, {%4,%5,%6,%7}, {%8,%9}, {%0,%1,%2,%3};\n"
                        : "+f"(acc[mt][nt][0]), "+f"(acc[mt][nt][1]),
                          "+f"(acc[mt][nt][2]), "+f"(acc[mt][nt][3])
                        : "r"(af[cur][mt][0]), "r"(af[cur][mt][1]),
                          "r"(af[cur][mt][2]), "r"(af[cur][mt][3]),
                          "r"(bf[cur][nt][0]), "r"(bf[cur][nt][1]));
        }
    }

    if (MODE == 0) {
#pragma unroll
        for (int mt = 0; mt < 2; mt++)
#pragma unroll
            for (int nt = 0; nt < 8; nt++) {
                int j = n0 + nbo + nt * 8 + tg * 2;   // [0,640)
#pragma unroll
                for (int h = 0; h < 2; h++) {
                    int row = m0 + mb + mt * 16 + g + h * 8;
                    if (row >= NEMB) continue;
                    float v0 = acc[mt][nt][h * 2 + 0];
                    float v1 = acc[mt][nt][h * 2 + 1];
                    if (j < 64) {
                        *(__half2*)(g_qh + (size_t)row * 64 + j) = __floats2half2_rn(v0, v1);
                    } else if (j < 128) {
                        *(__half2*)(g_keh + (size_t)row * 64 + (j - 64)) = __floats2half2_rn(v0, v1);
                    } else if (j < 384) {
                        v0 = 1.f / (1.f + __expf(-(v0 + bg[j - 128])));
                        v1 = 1.f / (1.f + __expf(-(v1 + bg[j - 127])));
                        *(__half2*)(g_gateh + (size_t)row * 256 + (j - 128)) = __floats2half2_rn(v0, v1);
                    } else {
                        v0 += bo[j - 384];
                        v1 += bo[j - 383];
                        *(float2*)(g_E1 + (size_t)row * 256 + (j - 384)) = make_float2(v0, v1);
                    }
                }
            }
    } else {
        // MODE 1: + E1(table) + center, fused LayerNorm
        float rs[4] = {0.f, 0.f, 0.f, 0.f};
        float rq[4] = {0.f, 0.f, 0.f, 0.f};
#pragma unroll
        for (int mt = 0; mt < 2; mt++)
#pragma unroll
            for (int h = 0; h < 2; h++) {
                int lr = mb + mt * 16 + g + h * 8;
                const float* cen = all_embs + (size_t)ridx[lr] * 256;
                const float* e1r = g_E1 + (size_t)ridx[lr] * 256;
                float s = 0.f, q = 0.f;
#pragma unroll
                for (int nt = 0; nt < 8; nt++) {
                    int j = nbo + nt * 8 + tg * 2;
                    float2 e1 = *(const float2*)(e1r + j);
                    float2 c2 = *(const float2*)(cen + j);
                    float v0 = acc[mt][nt][h * 2 + 0] + e1.x + c2.x;
                    float v1 = acc[mt][nt][h * 2 + 1] + e1.y + c2.y;
                    acc[mt][nt][h * 2 + 0] = v0;
                    acc[mt][nt][h * 2 + 1] = v1;
                    s += v0 + v1;
                    q += v0 * v0 + v1 * v1;
                }
                rs[mt * 2 + h] = s;
                rq[mt * 2 + h] = q;
            }
#pragma unroll
        for (int i = 0; i < 4; i++) {
            rs[i] += __shfl_xor_sync(0xffffffffu, rs[i], 1);
            rs[i] += __shfl_xor_sync(0xffffffffu, rs[i], 2);
            rq[i] += __shfl_xor_sync(0xffffffffu, rq[i], 1);
            rq[i] += __shfl_xor_sync(0xffffffffu, rq[i], 2);
        }
        const int nw = warp >> 2;
        if (tg == 0) {
#pragma unroll
            for (int mt = 0; mt < 2; mt++)
#pragma unroll
                for (int h = 0; h < 2; h++) {
                    int lr = mb + mt * 16 + g + h * 8;
                    redS[lr][nw] = rs[mt * 2 + h];
                    redQ[lr][nw] = rq[mt * 2 + h];
                }
        }
        __syncthreads();
        float mu[4], rstd[4];
#pragma unroll
        for (int mt = 0; mt < 2; mt++)
#pragma unroll
            for (int h = 0; h < 2; h++) {
                int lr = mb + mt * 16 + g + h * 8;
                float s = redS[lr][0] + redS[lr][1] + redS[lr][2] + redS[lr][3];
                float q = redQ[lr][0] + redQ[lr][1] + redQ[lr][2] + redQ[lr][3];
                float m = s * (1.f / 256.f);
                float v = q * (1.f / 256.f) - m * m;
                mu[mt * 2 + h] = m;
                rstd[mt * 2 + h] = rsqrtf(v + 1e-5f);
            }
#pragma unroll
        for (int mt = 0; mt < 2; mt++)
#pragma unroll
            for (int nt = 0; nt < 8; nt++) {
                int j = nbo + nt * 8 + tg * 2;
                float2 gm = *(const float2*)(gamma + j);
                float2 bt = *(const float2*)(beta + j);
#pragma unroll
                for (int h = 0; h < 2; h++) {
                    int row = m0 + mb + mt * 16 + g + h * 8;
                    float m = mu[mt * 2 + h], r = rstd[mt * 2 + h];
                    float o0 = (acc[mt][nt][h * 2 + 0] - m) * r * gm.x + bt.x;
                    float o1 = (acc[mt][nt][h * 2 + 1] - m) * r * gm.y + bt.y;
                    *(float2*)(out + (size_t)row * 256 + j) = make_float2(o0, o1);
                }
            }
    }
}

// ---------------- neigh: group-parallel logits + hfma2 streamed context ----
__global__ __launch_bounds__(256)
void neigh_kernel(const int* __restrict__ center_idx,
                  const int* __restrict__ nb_idx,
                  const float* __restrict__ nb_w) {
    const int warp = threadIdx.x >> 5;
    const int lane = threadIdx.x & 31;
    const int b = blockIdx.x * 8 + warp;
    const int grp = lane >> 3;
    const int u   = lane & 7;

    const int cidx = center_idx[b];

    // q fragment: dims [8u, 8u+8)
    uint4 qv = *(const uint4*)(g_qh + (size_t)cidx * 64 + u * 8);
    const __half2* qh = (const __half2*)&qv;
    float2 qf[4];
#pragma unroll
    for (int i = 0; i < 4; i++) qf[i] = __half22float2(qh[i]);

    int   myidx = 0;
    float myw   = 0.f;
    if (lane < 16) {
        myidx = nb_idx[b * 16 + lane];
        myw   = fmaxf(nb_w[b * 16 + lane], 1e-6f);
    }

    // group-parallel logits (fp32 dot)
    float v[4];
#pragma unroll
    for (int p = 0; p < 4; p++) {
        int r = __shfl_sync(0xffffffffu, myidx, p * 4 + grp);
        uint4 kv = *(const uint4*)(g_keh + (size_t)r * 64 + u * 8);
        const __half2* kh = (const __half2*)&kv;
        float s = 0.f;
#pragma unroll
        for (int i = 0; i < 4; i++) {
            float2 kf = __half22float2(kh[i]);
            s = fmaf(kf.x, qf[i].x, s);
            s = fmaf(kf.y, qf[i].y, s);
        }
        s += __shfl_xor_sync(0xffffffffu, s, 1);
        s += __shfl_xor_sync(0xffffffffu, s, 2);
        s += __shfl_xor_sync(0xffffffffu, s, 4);
        v[p] = s;
    }
    // collect: lane j (<16) wants v[j>>2] from lane (j&3)*8
    const int src = (lane & 3) * 8;
    float t0 = __shfl_sync(0xffffffffu, v[0], src);
    float t1 = __shfl_sync(0xffffffffu, v[1], src);
    float t2 = __shfl_sync(0xffffffffu, v[2], src);
    float t3 = __shfl_sync(0xffffffffu, v[3], src);
    const int sel = lane >> 2;
    float lgj = (sel == 0) ? t0 : (sel == 1) ? t1 : (sel == 2) ? t2 : t3;

    // softmax over 16 lanes (weights folded: w * exp(l - max))
    float l = (lane < 16) ? lgj * 0.125f : -1e30f;
    float mx = l;
#pragma unroll
    for (int off = 8; off >= 1; off >>= 1)
        mx = fmaxf(mx, __shfl_xor_sync(0xffffffffu, mx, off));
    float e = (lane < 16) ? myw * __expf(l - mx) : 0.f;
    float es = e;
#pragma unroll
    for (int off = 8; off >= 1; off >>= 1)
        es += __shfl_xor_sync(0xffffffffu, es, off);
    float ai = e / es;

    // context: hfma2 accumulation, two sets (even/odd k), fp32 combine.
    __half2 ai2 = __floats2half2_rn(ai, ai);
    uint32_t aiu = *(uint32_t*)&ai2;
    __half2 hacc[2][4];
#pragma unroll
    for (int s2 = 0; s2 < 2; s2++)
#pragma unroll
        for (int i = 0; i < 4; i++) hacc[s2][i] = __floats2half2_rn(0.f, 0.f);

#pragma unroll
    for (int k = 0; k < 16; k++) {
        int      r   = __shfl_sync(0xffffffffu, myidx, k);
        uint32_t aku = __shfl_sync(0xffffffffu, aiu, k);
        __half2  akh = *(__half2*)&aku;
        uint4 nv = *(const uint4*)(g_embh + (size_t)r * 256 + lane * 8);
        const __half2* hp = (const __half2*)&nv;
        const int s2 = k & 1;
#pragma unroll
        for (int i = 0; i < 4; i++)
            hacc[s2][i] = __hfma2(hp[i], akh, hacc[s2][i]);
    }

    float a[8];
#pragma unroll
    for (int i = 0; i < 4; i++) {
        float2 f0 = __half22float2(hacc[0][i]);
        float2 f1 = __half22float2(hacc[1][i]);
        a[2 * i + 0] = f0.x + f1.x;
        a[2 * i + 1] = f0.y + f1.y;
    }

    // gate (fp16 table) multiply, fp16 store
    uint4 gv = *(const uint4*)(g_gateh + (size_t)cidx * 256 + lane * 8);
    const __half2* gh = (const __half2*)&gv;
    __half2 hout[4];
#pragma unroll
    for (int i = 0; i < 4; i++) {
        float2 gf = __half22float2(gh[i]);
        hout[i] = __floats2half2_rn(gf.x * a[2 * i + 0], gf.y * a[2 * i + 1]);
    }
    *(uint4*)(g_ctxh + (size_t)b * 256 + lane * 8) = *(uint4*)hout;
}

// ---------------- launch ---------------------------------------------------
extern "C" void kernel_launch(void* const* d_in, const int* in_sizes, int n_in,
                              void* d_out, int out_size) {
    const float* all_embs   = (const float*)d_in[0];
    const int*   center_idx = (const int*)d_in[1];
    const int*   nb_idx     = (const int*)d_in[2];
    const float* nb_w       = (const float*)d_in[3];
    const float* Wq         = (const float*)d_in[4];
    const float* Wk         = (const float*)d_in[5];
    const float* Wg         = (const float*)d_in[6];
    const float* bg         = (const float*)d_in[7];
    const float* Wo         = (const float*)d_in[8];
    const float* bo         = (const float*)d_in[9];
    const float* gamma      = (const float*)d_in[10];
    const float* beta       = (const float*)d_in[11];
    float* out = (float*)d_out;

    const int sm128 = 2 * (128 + 128) * RPITCH;   // 73728
    const int sm256 = 2 * (128 + 256) * RPITCH;   // 110592

    static int configured = 0;
    if (!configured) {
        cudaFuncSetAttribute((const void*)gemm_kernel<0, 128, 256>,
                             cudaFuncAttributeMaxDynamicSharedMemorySize, sm128);
        cudaFuncSetAttribute((const void*)gemm_kernel<1, 256, 512>,
                             cudaFuncAttributeMaxDynamicSharedMemorySize, sm256);
        configured = 1;
    }

    prep_kernel<<<896 + 2500, 256>>>(Wq, Wk, Wg, Wo, all_embs);
    gemm_kernel<0, 128, 256><<<dim3((NEMB + 127) / 128, 5), 256, sm128>>>(
        all_embs, center_idx, bg, bo, gamma, beta, nullptr);                 // tables q|ke|gate|E1
    neigh_kernel<<<BATCH / 8, 256>>>(center_idx, nb_idx, nb_w);
    gemm_kernel<1, 256, 512><<<dim3(BATCH / 128, 1), 512, sm256>>>(
        all_embs, center_idx, bg, bo, gamma, beta, out);                     // out + LN
}

// round 14
// speedup vs baseline: 2.6011x; 1.0428x over previous
#include <cuda_runtime.h>
#include <cuda_fp16.h>
#include <cstdint>

#define BATCH 32768
#define NEMB  20000
#define RPITCH 144                 // bytes per smem row (64 halfs used + pad)
#define A_BYTES (128 * RPITCH)

// ---------------- device scratch (static, allocation-free) ----------------
__device__ __align__(128) __half g_WTh[640 * 256];           // Wq|Wk|Wg|Wo1 rows (fp16)
__device__ __align__(128) __half g_W2h[256 * 256];           // Wo2 (fp16)
__device__ __align__(128) __half g_embh[(size_t)NEMB * 256]; // fp16 embedding copy
__device__ __align__(128) __half g_qh[(size_t)NEMB * 64];    // fp16 q table
__device__ __align__(128) __half g_keh[(size_t)NEMB * 64];   // fp16 ke table
__device__ __align__(128) __half g_gateh[(size_t)NEMB * 256];// fp16 gate table
__device__ __align__(128) float  g_E1c[(size_t)NEMB * 256];  // fp32 E1 + bo + emb table
__device__ __align__(128) __half g_ctxh[(size_t)BATCH * 256];// gated context (fp16)

__device__ __forceinline__ void cp_async16(uint32_t smem_dst, const void* gmem_src) {
    asm volatile("cp.async.cg.shared.global [%0], [%1], 16;\n" :: "r"(smem_dst), "l"(gmem_src));
}
__device__ __forceinline__ void ldsm_x4(uint32_t& r0, uint32_t& r1, uint32_t& r2, uint32_t& r3,
                                        uint32_t saddr) {
    asm volatile("ldmatrix.sync.aligned.m8n8.x4.shared.b16 {%0,%1,%2,%3}, [%4];"
                 : "=r"(r0), "=r"(r1), "=r"(r2), "=r"(r3) : "r"(saddr));
}

// ---------------- K0: fp16 weight assembly + fp16 embedding copy -----------
__global__ void prep_kernel(const float* __restrict__ Wq, const float* __restrict__ Wk,
                            const float* __restrict__ Wg, const float* __restrict__ Wo,
                            const float* __restrict__ embs) {
    int j = blockIdx.x;
    int e = threadIdx.x;
    if (j < 64)        g_WTh[j * 256 + e] = __float2half_rn(Wq[j * 256 + e]);
    else if (j < 128)  g_WTh[j * 256 + e] = __float2half_rn(Wk[(j - 64) * 256 + e]);
    else if (j < 384)  g_WTh[j * 256 + e] = __float2half_rn(Wg[(j - 128) * 256 + e]);
    else if (j < 640)  g_WTh[j * 256 + e] = __float2half_rn(Wo[(j - 384) * 512 + e]);
    else if (j < 896)  g_W2h[(j - 640) * 256 + e] = __float2half_rn(Wo[(j - 640) * 512 + 256 + e]);
    else {
        // embedding convert: blocks [896, 896+2500)
        size_t i = ((size_t)(j - 896) * 256 + e) * 8;
        float4 f0 = *(const float4*)(embs + i);
        float4 f1 = *(const float4*)(embs + i + 4);
        __half2 h[4];
        h[0] = __floats2half2_rn(f0.x, f0.y);
        h[1] = __floats2half2_rn(f0.z, f0.w);
        h[2] = __floats2half2_rn(f1.x, f1.y);
        h[3] = __floats2half2_rn(f1.z, f1.w);
        *(uint4*)(g_embh + i) = *(uint4*)h;
    }
}

// ---------------- GEMM template (fp16 m16n8k16, 2-stage cp.async) ----------
// MODE 0: A = g_embh (contiguous), B = g_WTh slab (nbase selects slabs)
//         -> fp16 q/ke/gate + fp32 E1c (= E1 + bo + emb)
// MODE 1: A = g_ctxh, B = g_W2h -> + E1c(table), fused LN -> out
template <int MODE, int BROWS, int NTH>
__global__ __launch_bounds__(NTH, (NTH == 512) ? 1 : 2)
void gemm_kernel(const float* __restrict__ all_embs,
                 const int* __restrict__ center_idx,
                 const float* __restrict__ bg,
                 const float* __restrict__ bo,
                 const float* __restrict__ gamma,
                 const float* __restrict__ beta,
                 float* __restrict__ out,
                 int nbase) {
    constexpr int STAGE_BYTES = (128 + BROWS) * RPITCH;
    extern __shared__ char sm[];
    __shared__ int   ridx[128];
    __shared__ float redS[128][4];
    __shared__ float redQ[128][4];

    const int t    = threadIdx.x;
    const int lane = t & 31;
    const int warp = t >> 5;
    const int m0 = blockIdx.x * 128;
    const int n0 = (nbase + blockIdx.y) * BROWS;
    const __half* Bmat = (MODE == 0) ? (g_WTh + (size_t)n0 * 256) : g_W2h;

    if (MODE == 1 && t < 128) ridx[t] = center_idx[m0 + t];
    __syncthreads();

    const uint32_t sm_u32 = (uint32_t)__cvta_generic_to_shared(sm);
    const int g   = lane >> 2;
    const int tg  = lane & 3;
    const int mb  = (warp & 3) * 32;
    const int nbo = (warp >> 2) * 64;

    uint32_t a_off[2], b_off[4];
#pragma unroll
    for (int mt = 0; mt < 2; mt++)
        a_off[mt] = (mb + mt * 16 + (lane & 15)) * RPITCH + ((lane >> 4) & 1) * 16;
#pragma unroll
    for (int p = 0; p < 4; p++)
        b_off[p] = A_BYTES + (nbo + p * 16 + ((lane >> 4) & 1) * 8 + (lane & 7)) * RPITCH
                   + ((lane >> 3) & 1) * 16;

    auto load_stage = [&](int kt, int s) {
        const uint32_t dst0 = sm_u32 + s * STAGE_BYTES;
        const int kk = kt * 64;                      // halfs
        for (int idx = t; idx < 128 * 8; idx += NTH) {
            int row = idx >> 3, ch = idx & 7;
            const __half* src;
            if (MODE == 0) {
                int r = m0 + row; if (r >= NEMB) r = NEMB - 1;
                src = g_embh + (size_t)r * 256 + kk + ch * 8;
            } else {
                src = g_ctxh + (size_t)(m0 + row) * 256 + kk + ch * 8;
            }
            cp_async16(dst0 + row * RPITCH + ch * 16, src);
        }
        for (int idx = t; idx < BROWS * 8; idx += NTH) {
            int row = idx >> 3, ch = idx & 7;
            cp_async16(dst0 + A_BYTES + row * RPITCH + ch * 16,
                       Bmat + (size_t)row * 256 + kk + ch * 8);
        }
    };

    float acc[2][8][4] = {};
    uint32_t af[2][2][4];
    uint32_t bf[2][8][2];

    auto load_frags = [&](uint32_t stage, int ks, int buf) {
        const uint32_t kbyte = ks * 32;              // 16 halfs
#pragma unroll
        for (int mt = 0; mt < 2; mt++)
            ldsm_x4(af[buf][mt][0], af[buf][mt][1], af[buf][mt][2], af[buf][mt][3],
                    stage + a_off[mt] + kbyte);
#pragma unroll
        for (int p = 0; p < 4; p++)
            ldsm_x4(bf[buf][2 * p][0], bf[buf][2 * p][1], bf[buf][2 * p + 1][0],
                    bf[buf][2 * p + 1][1], stage + b_off[p] + kbyte);
    };

    load_stage(0, 0);
    asm volatile("cp.async.commit_group;\n" ::: "memory");

#pragma unroll 1
    for (int it = 0; it < 4; ++it) {
        const int s = it & 1;
        asm volatile("cp.async.wait_group 0;\n" ::: "memory");
        __syncthreads();
        if (it + 1 < 4) load_stage(it + 1, s ^ 1);
        asm volatile("cp.async.commit_group;\n" ::: "memory");

        const uint32_t stage = sm_u32 + s * STAGE_BYTES;
        load_frags(stage, 0, 0);
#pragma unroll
        for (int ks = 0; ks < 4; ks++) {
            const int cur = ks & 1;
            if (ks < 3) load_frags(stage, ks + 1, cur ^ 1);
#pragma unroll
            for (int mt = 0; mt < 2; mt++)
#pragma unroll
                for (int nt = 0; nt < 8; nt++)
                    asm volatile(
                        "mma.sync.aligned.m16n8k16.row.col.f32.f16.f16.f32 "
                        "{%0,%1,%2,%3}, {%4,%5,%6,%7}, {%8,%9}, {%0,%1,%2,%3};\n"
                        : "+f"(acc[mt][nt][0]), "+f"(acc[mt][nt][1]),
                          "+f"(acc[mt][nt][2]), "+f"(acc[mt][nt][3])
                        : "r"(af[cur][mt][0]), "r"(af[cur][mt][1]),
                          "r"(af[cur][mt][2]), "r"(af[cur][mt][3]),
                          "r"(bf[cur][nt][0]), "r"(bf[cur][nt][1]));
        }
    }

    if (MODE == 0) {
#pragma unroll
        for (int mt = 0; mt < 2; mt++)
#pragma unroll
            for (int nt = 0; nt < 8; nt++) {
                int j = n0 + nbo + nt * 8 + tg * 2;   // [0,640)
#pragma unroll
                for (int h = 0; h < 2; h++) {
                    int row = m0 + mb + mt * 16 + g + h * 8;
                    if (row >= NEMB) continue;
                    float v0 = acc[mt][nt][h * 2 + 0];
                    float v1 = acc[mt][nt][h * 2 + 1];
                    if (j < 64) {
                        *(__half2*)(g_qh + (size_t)row * 64 + j) = __floats2half2_rn(v0, v1);
                    } else if (j < 128) {
                        *(__half2*)(g_keh + (size_t)row * 64 + (j - 64)) = __floats2half2_rn(v0, v1);
                    } else if (j < 384) {
                        v0 = 1.f / (1.f + __expf(-(v0 + bg[j - 128])));
                        v1 = 1.f / (1.f + __expf(-(v1 + bg[j - 127])));
                        *(__half2*)(g_gateh + (size_t)row * 256 + (j - 128)) = __floats2half2_rn(v0, v1);
                    } else {
                        // E1c = E1 + bo + emb  (center residual folded in)
                        float2 em = *(const float2*)(all_embs + (size_t)row * 256 + (j - 384));
                        v0 += bo[j - 384] + em.x;
                        v1 += bo[j - 383] + em.y;
                        *(float2*)(g_E1c + (size_t)row * 256 + (j - 384)) = make_float2(v0, v1);
                    }
                }
            }
    } else {
        // MODE 1: + E1c(table), fused LayerNorm
        float rs[4] = {0.f, 0.f, 0.f, 0.f};
        float rq[4] = {0.f, 0.f, 0.f, 0.f};
#pragma unroll
        for (int mt = 0; mt < 2; mt++)
#pragma unroll
            for (int h = 0; h < 2; h++) {
                int lr = mb + mt * 16 + g + h * 8;
                const float* e1r = g_E1c + (size_t)ridx[lr] * 256;
                float s = 0.f, q = 0.f;
#pragma unroll
                for (int nt = 0; nt < 8; nt++) {
                    int j = nbo + nt * 8 + tg * 2;
                    float2 e1 = *(const float2*)(e1r + j);
                    float v0 = acc[mt][nt][h * 2 + 0] + e1.x;
                    float v1 = acc[mt][nt][h * 2 + 1] + e1.y;
                    acc[mt][nt][h * 2 + 0] = v0;
                    acc[mt][nt][h * 2 + 1] = v1;
                    s += v0 + v1;
                    q += v0 * v0 + v1 * v1;
                }
                rs[mt * 2 + h] = s;
                rq[mt * 2 + h] = q;
            }
#pragma unroll
        for (int i = 0; i < 4; i++) {
            rs[i] += __shfl_xor_sync(0xffffffffu, rs[i], 1);
            rs[i] += __shfl_xor_sync(0xffffffffu, rs[i], 2);
            rq[i] += __shfl_xor_sync(0xffffffffu, rq[i], 1);
            rq[i] += __shfl_xor_sync(0xffffffffu, rq[i], 2);
        }
        const int nw = warp >> 2;
        if (tg == 0) {
#pragma unroll
            for (int mt = 0; mt < 2; mt++)
#pragma unroll
                for (int h = 0; h < 2; h++) {
                    int lr = mb + mt * 16 + g + h * 8;
                    redS[lr][nw] = rs[mt * 2 + h];
                    redQ[lr][nw] = rq[mt * 2 + h];
                }
        }
        __syncthreads();
        float mu[4], rstd[4];
#pragma unroll
        for (int mt = 0; mt < 2; mt++)
#pragma unroll
            for (int h = 0; h < 2; h++) {
                int lr = mb + mt * 16 + g + h * 8;
                float s = redS[lr][0] + redS[lr][1] + redS[lr][2] + redS[lr][3];
                float q = redQ[lr][0] + redQ[lr][1] + redQ[lr][2] + redQ[lr][3];
                float m = s * (1.f / 256.f);
                float v = q * (1.f / 256.f) - m * m;
                mu[mt * 2 + h] = m;
                rstd[mt * 2 + h] = rsqrtf(v + 1e-5f);
            }
#pragma unroll
        for (int mt = 0; mt < 2; mt++)
#pragma unroll
            for (int nt = 0; nt < 8; nt++) {
                int j = nbo + nt * 8 + tg * 2;
                float2 gm = *(const float2*)(gamma + j);
                float2 bt = *(const float2*)(beta + j);
#pragma unroll
                for (int h = 0; h < 2; h++) {
                    int row = m0 + mb + mt * 16 + g + h * 8;
                    float m = mu[mt * 2 + h], r = rstd[mt * 2 + h];
                    float o0 = (acc[mt][nt][h * 2 + 0] - m) * r * gm.x + bt.x;
                    float o1 = (acc[mt][nt][h * 2 + 1] - m) * r * gm.y + bt.y;
                    *(float2*)(out + (size_t)row * 256 + j) = make_float2(o0, o1);
                }
            }
    }
}

// ---------------- neigh: group-parallel logits + hfma2 streamed context ----
__global__ __launch_bounds__(256)
void neigh_kernel(const int* __restrict__ center_idx,
                  const int* __restrict__ nb_idx,
                  const float* __restrict__ nb_w) {
    const int warp = threadIdx.x >> 5;
    const int lane = threadIdx.x & 31;
    const int b = blockIdx.x * 8 + warp;
    const int grp = lane >> 3;
    const int u   = lane & 7;

    const int cidx = center_idx[b];

    // q fragment: dims [8u, 8u+8)
    uint4 qv = *(const uint4*)(g_qh + (size_t)cidx * 64 + u * 8);
    const __half2* qh = (const __half2*)&qv;
    float2 qf[4];
#pragma unroll
    for (int i = 0; i < 4; i++) qf[i] = __half22float2(qh[i]);

    int   myidx = 0;
    float myw   = 0.f;
    if (lane < 16) {
        myidx = nb_idx[b * 16 + lane];
        myw   = fmaxf(nb_w[b * 16 + lane], 1e-6f);
    }

    // group-parallel logits (fp32 dot)
    float v[4];
#pragma unroll
    for (int p = 0; p < 4; p++) {
        int r = __shfl_sync(0xffffffffu, myidx, p * 4 + grp);
        uint4 kv = *(const uint4*)(g_keh + (size_t)r * 64 + u * 8);
        const __half2* kh = (const __half2*)&kv;
        float s = 0.f;
#pragma unroll
        for (int i = 0; i < 4; i++) {
            float2 kf = __half22float2(kh[i]);
            s = fmaf(kf.x, qf[i].x, s);
            s = fmaf(kf.y, qf[i].y, s);
        }
        s += __shfl_xor_sync(0xffffffffu, s, 1);
        s += __shfl_xor_sync(0xffffffffu, s, 2);
        s += __shfl_xor_sync(0xffffffffu, s, 4);
        v[p] = s;
    }
    // collect: lane j (<16) wants v[j>>2] from lane (j&3)*8
    const int src = (lane & 3) * 8;
    float t0 = __shfl_sync(0xffffffffu, v[0], src);
    float t1 = __shfl_sync(0xffffffffu, v[1], src);
    float t2 = __shfl_sync(0xffffffffu, v[2], src);
    float t3 = __shfl_sync(0xffffffffu, v[3], src);
    const int sel = lane >> 2;
    float lgj = (sel == 0) ? t0 : (sel == 1) ? t1 : (sel == 2) ? t2 : t3;

    // softmax over 16 lanes (weights folded: w * exp(l - max))
    float l = (lane < 16) ? lgj * 0.125f : -1e30f;
    float mx = l;
#pragma unroll
    for (int off = 8; off >= 1; off >>= 1)
        mx = fmaxf(mx, __shfl_xor_sync(0xffffffffu, mx, off));
    float e = (lane < 16) ? myw * __expf(l - mx) : 0.f;
    float es = e;
#pragma unroll
    for (int off = 8; off >= 1; off >>= 1)
        es += __shfl_xor_sync(0xffffffffu, es, off);
    float ai = e / es;

    // context: hfma2 accumulation, two sets (even/odd k), fp32 combine.
    __half2 ai2 = __floats2half2_rn(ai, ai);
    uint32_t aiu = *(uint32_t*)&ai2;
    __half2 hacc[2][4];
#pragma unroll
    for (int s2 = 0; s2 < 2; s2++)
#pragma unroll
        for (int i = 0; i < 4; i++) hacc[s2][i] = __floats2half2_rn(0.f, 0.f);

#pragma unroll
    for (int k = 0; k < 16; k++) {
        int      r   = __shfl_sync(0xffffffffu, myidx, k);
        uint32_t aku = __shfl_sync(0xffffffffu, aiu, k);
        __half2  akh = *(__half2*)&aku;
        uint4 nv = *(const uint4*)(g_embh + (size_t)r * 256 + lane * 8);
        const __half2* hp = (const __half2*)&nv;
        const int s2 = k & 1;
#pragma unroll
        for (int i = 0; i < 4; i++)
            hacc[s2][i] = __hfma2(hp[i], akh, hacc[s2][i]);
    }

    float a[8];
#pragma unroll
    for (int i = 0; i < 4; i++) {
        float2 f0 = __half22float2(hacc[0][i]);
        float2 f1 = __half22float2(hacc[1][i]);
        a[2 * i + 0] = f0.x + f1.x;
        a[2 * i + 1] = f0.y + f1.y;
    }

    // gate (fp16 table) multiply, fp16 store
    uint4 gv = *(const uint4*)(g_gateh + (size_t)cidx * 256 + lane * 8);
    const __half2* gh = (const __half2*)&gv;
    __half2 hout[4];
#pragma unroll
    for (int i = 0; i < 4; i++) {
        float2 gf = __half22float2(gh[i]);
        hout[i] = __floats2half2_rn(gf.x * a[2 * i + 0], gf.y * a[2 * i + 1]);
    }
    *(uint4*)(g_ctxh + (size_t)b * 256 + lane * 8) = *(uint4*)hout;
}

// ---------------- launch ---------------------------------------------------
extern "C" void kernel_launch(void* const* d_in, const int* in_sizes, int n_in,
                              void* d_out, int out_size) {
    const float* all_embs   = (const float*)d_in[0];
    const int*   center_idx = (const int*)d_in[1];
    const int*   nb_idx     = (const int*)d_in[2];
    const float* nb_w       = (const float*)d_in[3];
    const float* Wq         = (const float*)d_in[4];
    const float* Wk         = (const float*)d_in[5];
    const float* Wg         = (const float*)d_in[6];
    const float* bg         = (const float*)d_in[7];
    const float* Wo         = (const float*)d_in[8];
    const float* bo         = (const float*)d_in[9];
    const float* gamma      = (const float*)d_in[10];
    const float* beta       = (const float*)d_in[11];
    float* out = (float*)d_out;

    const int sm128 = 2 * (128 + 128) * RPITCH;   // 73728
    const int sm256 = 2 * (128 + 256) * RPITCH;   // 110592

    static cudaStream_t s2 = nullptr;
    static cudaEvent_t ev1 = nullptr, ev2 = nullptr;
    static int configured = 0;
    if (!configured) {
        cudaFuncSetAttribute((const void*)gemm_kernel<0, 128, 256>,
                             cudaFuncAttributeMaxDynamicSharedMemorySize, sm128);
        cudaFuncSetAttribute((const void*)gemm_kernel<1, 256, 512>,
                             cudaFuncAttributeMaxDynamicSharedMemorySize, sm256);
        cudaStreamCreateWithFlags(&s2, cudaStreamNonBlocking);
        cudaEventCreateWithFlags(&ev1, cudaEventDisableTiming);
        cudaEventCreateWithFlags(&ev2, cudaEventDisableTiming);
        configured = 1;
    }

    // main stream: prep -> gemm0a(q/ke/gate) -> neigh -> [join] -> gemm1
    // side stream: [fork after prep] gemm0b(E1c slabs) -> [join]
    prep_kernel<<<896 + 2500, 256>>>(Wq, Wk, Wg, Wo, all_embs);
    cudaEventRecord(ev1, 0);
    cudaStreamWaitEvent(s2, ev1, 0);

    gemm_kernel<0, 128, 256><<<dim3((NEMB + 127) / 128, 3), 256, sm128>>>(
        all_embs, center_idx, bg, bo, gamma, beta, nullptr, 0);      // q|ke|gate slabs
    gemm_kernel<0, 128, 256><<<dim3((NEMB + 127) / 128, 2), 256, sm128, s2>>>(
        all_embs, center_idx, bg, bo, gamma, beta, nullptr, 3);      // E1c slabs (overlapped)

    neigh_kernel<<<BATCH / 8, 256>>>(center_idx, nb_idx, nb_w);

    cudaEventRecord(ev2, s2);
    cudaStreamWaitEvent(0, ev2, 0);
    gemm_kernel<1, 256, 512><<<dim3(BATCH / 128, 1), 512, sm256>>>(
        all_embs, center_idx, bg, bo, gamma, beta, out, 0);          // out + LN
}